// round 2
// baseline (speedup 1.0000x reference)
#include <cuda_runtime.h>
#include <cstddef>

// Problem constants
#define SQ   1024          // sequence length S
#define BB   8             // batch B
#define EE   1024          // embed E
#define HH   16            // heads
#define DD   64            // head dim
#define DFF  4096
#define MTOK (SQ * BB)     // 8192 token rows
#define E3   (3 * EE)      // 3072

// ---------------------------------------------------------------------------
// Scratch (no allocations allowed -> __device__ globals)
// ---------------------------------------------------------------------------
__device__ float g_qkv[(size_t)MTOK * E3];     // 96 MB
__device__ float g_ctx[(size_t)MTOK * EE];     // 32 MB
__device__ float g_tmp[(size_t)MTOK * EE];     // attn_out, later ff2_out
__device__ float g_x  [(size_t)MTOK * EE];     // ln1 output
__device__ float g_ff1[(size_t)MTOK * DFF];    // 128 MB

// ---------------------------------------------------------------------------
// GEMM: C[M,N] = A[M,K] @ B[N,K]^T + bias[N]   (both A and B row-major, K inner)
// EPI: 0 = bias, 1 = bias + relu
// Tiles: 128x128, BK=8, 256 threads, 8x8 per-thread micro-tile.
// M, N multiples of 128; K multiple of 8 (and of 4 for float4 loads).
// ---------------------------------------------------------------------------
template <int EPI>
__global__ __launch_bounds__(256, 2)
void gemm_kernel(const float* __restrict__ A, const float* __restrict__ Bm,
                 const float* __restrict__ bias, float* __restrict__ C,
                 int Mdim, int Ndim, int Kdim)
{
    __shared__ float As[8][128];
    __shared__ float Bs[8][128];

    const int bm = blockIdx.y * 128;
    const int bn = blockIdx.x * 128;
    const int t  = threadIdx.x;
    const int tx = t & 15;        // 0..15  -> N micro
    const int ty = t >> 4;        // 0..15  -> M micro

    // loader: thread t covers row lr (0..127), k-quad lc (0 or 4)
    const int lr = t >> 1;
    const int lc = (t & 1) * 4;

    const float* Aptr = A + (size_t)(bm + lr) * Kdim + lc;
    const float* Bptr = Bm + (size_t)(bn + lr) * Kdim + lc;

    float acc[8][8];
#pragma unroll
    for (int i = 0; i < 8; i++)
#pragma unroll
        for (int j = 0; j < 8; j++) acc[i][j] = 0.0f;

    for (int k0 = 0; k0 < Kdim; k0 += 8) {
        float4 a4 = *(const float4*)(Aptr + k0);
        float4 b4 = *(const float4*)(Bptr + k0);
        As[lc + 0][lr] = a4.x; As[lc + 1][lr] = a4.y;
        As[lc + 2][lr] = a4.z; As[lc + 3][lr] = a4.w;
        Bs[lc + 0][lr] = b4.x; Bs[lc + 1][lr] = b4.y;
        Bs[lc + 2][lr] = b4.z; Bs[lc + 3][lr] = b4.w;
        __syncthreads();

#pragma unroll
        for (int kk = 0; kk < 8; kk++) {
            float4 a0 = *(const float4*)&As[kk][ty * 8];
            float4 a1 = *(const float4*)&As[kk][ty * 8 + 4];
            float4 b0 = *(const float4*)&Bs[kk][tx * 8];
            float4 b1 = *(const float4*)&Bs[kk][tx * 8 + 4];
            float ar[8] = {a0.x, a0.y, a0.z, a0.w, a1.x, a1.y, a1.z, a1.w};
            float br[8] = {b0.x, b0.y, b0.z, b0.w, b1.x, b1.y, b1.z, b1.w};
#pragma unroll
            for (int i = 0; i < 8; i++)
#pragma unroll
                for (int j = 0; j < 8; j++)
                    acc[i][j] = fmaf(ar[i], br[j], acc[i][j]);
        }
        __syncthreads();
    }

    float bi[8];
#pragma unroll
    for (int j = 0; j < 8; j++) bi[j] = bias[bn + tx * 8 + j];

#pragma unroll
    for (int i = 0; i < 8; i++) {
        float* Crow = C + (size_t)(bm + ty * 8 + i) * Ndim + bn + tx * 8;
#pragma unroll
        for (int j = 0; j < 8; j++) {
            float v = acc[i][j] + bi[j];
            if (EPI == 1) v = fmaxf(v, 0.0f);
            Crow[j] = v;
        }
    }
}

// ---------------------------------------------------------------------------
// Flash attention, fp32, online softmax.
// grid = B*H*(S/64) blocks, 256 threads.
// Block handles 64 query rows of one head, streams keys in 32-row tiles.
// Thread t: query row r = t>>2, quadrant q = t&3.
//   S compute : thread owns keys  k = q*8 + j   (j 0..7)
//   PV compute: thread owns dims  d = q + dd*4  (dd 0..15)
// ---------------------------------------------------------------------------
__global__ __launch_bounds__(256)
void attn_kernel(const float* __restrict__ qkv, float* __restrict__ ctx)
{
    __shared__ float Qs[64][64];
    __shared__ float Ks[32][65];   // pad 65: 8-row stride -> distinct banks
    __shared__ float Vs[32][64];
    __shared__ float Ps[64][33];

    const int qt = blockIdx.x & 15;       // q tile 0..15
    const int bh = blockIdx.x >> 4;       // 0..127
    const int b  = bh / HH;
    const int h  = bh % HH;

    const int t = threadIdx.x;
    const int r = t >> 2;                 // query row 0..63
    const int q = t & 3;

    const size_t rowstride = (size_t)BB * E3;   // stride between s and s+1
    const float* Qg = qkv + ((size_t)(qt * 64) * BB + b) * E3 + h * DD;
    const float* Kg = qkv + (size_t)b * E3 + EE + h * DD;
    const float* Vg = Kg + EE;

    // load Q tile, pre-scaled by 1/sqrt(D) = 0.125
#pragma unroll
    for (int i = 0; i < 16; i++) {
        int e = t + i * 256;              // 0..4095
        int row = e >> 6, col = e & 63;
        Qs[row][col] = Qg[(size_t)row * rowstride + col] * 0.125f;
    }

    float o[16];
#pragma unroll
    for (int dd = 0; dd < 16; dd++) o[dd] = 0.0f;
    float m_i = -1e30f, l_i = 0.0f;

    __syncthreads();

    for (int kt = 0; kt < SQ / 32; kt++) {
        // load K,V tiles
#pragma unroll
        for (int i = 0; i < 8; i++) {
            int e = t + i * 256;          // 0..2047
            int row = e >> 6, col = e & 63;
            size_t goff = (size_t)(kt * 32 + row) * rowstride + col;
            Ks[row][col] = Kg[goff];
            Vs[row][col] = Vg[goff];
        }
        __syncthreads();

        // S = Q K^T  (thread: 8 keys)
        float sacc[8] = {0, 0, 0, 0, 0, 0, 0, 0};
        const int kb = q * 8;
#pragma unroll 8
        for (int d = 0; d < 64; d++) {
            float qd = Qs[r][d];
#pragma unroll
            for (int j = 0; j < 8; j++)
                sacc[j] = fmaf(qd, Ks[kb + j][d], sacc[j]);
        }

        // online softmax for this row (4 lanes per row, contiguous in warp)
        float tmax = sacc[0];
#pragma unroll
        for (int j = 1; j < 8; j++) tmax = fmaxf(tmax, sacc[j]);
        tmax = fmaxf(tmax, __shfl_xor_sync(0xffffffffu, tmax, 1));
        tmax = fmaxf(tmax, __shfl_xor_sync(0xffffffffu, tmax, 2));

        float new_m = fmaxf(m_i, tmax);
        float corr  = __expf(m_i - new_m);

        float tsum = 0.0f;
        float p[8];
#pragma unroll
        for (int j = 0; j < 8; j++) {
            p[j] = __expf(sacc[j] - new_m);
            tsum += p[j];
        }
        tsum += __shfl_xor_sync(0xffffffffu, tsum, 1);
        tsum += __shfl_xor_sync(0xffffffffu, tsum, 2);

        l_i = l_i * corr + tsum;
        m_i = new_m;
#pragma unroll
        for (int dd = 0; dd < 16; dd++) o[dd] *= corr;
#pragma unroll
        for (int j = 0; j < 8; j++) Ps[r][kb + j] = p[j];
        __syncthreads();

        // O += P @ V   (thread: 16 dims, d = q + dd*4 -> conflict-free Vs)
#pragma unroll 4
        for (int k = 0; k < 32; k++) {
            float pv = Ps[r][k];
#pragma unroll
            for (int dd = 0; dd < 16; dd++)
                o[dd] = fmaf(pv, Vs[k][q + dd * 4], o[dd]);
        }
        __syncthreads();
    }

    float inv_l = 1.0f / l_i;
    const int srow = qt * 64 + r;
    float* Cp = ctx + ((size_t)srow * BB + b) * EE + h * DD;
#pragma unroll
    for (int dd = 0; dd < 16; dd++)
        Cp[q + dd * 4] = o[dd] * inv_l;
}

// ---------------------------------------------------------------------------
// out = layernorm(a + b) * g + beta, one block per row of 1024
// ---------------------------------------------------------------------------
__global__ __launch_bounds__(256)
void add_ln_kernel(const float* __restrict__ a, const float* __restrict__ bres,
                   const float* __restrict__ g, const float* __restrict__ beta,
                   float* __restrict__ out)
{
    const int row = blockIdx.x;
    const int t   = threadIdx.x;
    const float4* A4 = (const float4*)(a    + (size_t)row * EE);
    const float4* B4 = (const float4*)(bres + (size_t)row * EE);

    float4 x = A4[t];
    float4 y = B4[t];
    x.x += y.x; x.y += y.y; x.z += y.z; x.w += y.w;

    float s  = x.x + x.y + x.z + x.w;
    float ss = x.x * x.x + x.y * x.y + x.z * x.z + x.w * x.w;

#pragma unroll
    for (int off = 16; off > 0; off >>= 1) {
        s  += __shfl_xor_sync(0xffffffffu, s,  off);
        ss += __shfl_xor_sync(0xffffffffu, ss, off);
    }
    __shared__ float sh_s[8], sh_ss[8];
    const int w = t >> 5, l = t & 31;
    if (l == 0) { sh_s[w] = s; sh_ss[w] = ss; }
    __syncthreads();
    s = 0.0f; ss = 0.0f;
#pragma unroll
    for (int i = 0; i < 8; i++) { s += sh_s[i]; ss += sh_ss[i]; }

    const float mean = s * (1.0f / EE);
    const float var  = ss * (1.0f / EE) - mean * mean;
    const float rstd = rsqrtf(var + 1e-5f);

    float4 g4 = ((const float4*)g)[t];
    float4 b4 = ((const float4*)beta)[t];
    float4 o;
    o.x = (x.x - mean) * rstd * g4.x + b4.x;
    o.y = (x.y - mean) * rstd * g4.y + b4.y;
    o.z = (x.z - mean) * rstd * g4.z + b4.z;
    o.w = (x.w - mean) * rstd * g4.w + b4.w;
    ((float4*)(out + (size_t)row * EE))[t] = o;
}

// ---------------------------------------------------------------------------
// launch
// ---------------------------------------------------------------------------
extern "C" void kernel_launch(void* const* d_in, const int* in_sizes, int n_in,
                              void* d_out, int out_size)
{
    const float* src    = (const float*)d_in[0];
    const float* in_w   = (const float*)d_in[1];
    const float* in_b   = (const float*)d_in[2];
    const float* out_w  = (const float*)d_in[3];
    const float* out_b  = (const float*)d_in[4];
    const float* ln1g   = (const float*)d_in[5];
    const float* ln1b   = (const float*)d_in[6];
    const float* ln2g   = (const float*)d_in[7];
    const float* ln2b   = (const float*)d_in[8];
    const float* w1     = (const float*)d_in[9];
    const float* b1     = (const float*)d_in[10];
    const float* w2     = (const float*)d_in[11];
    const float* b2     = (const float*)d_in[12];
    float* out = (float*)d_out;

    float *qkv, *ctx, *tmp, *x, *ff1;
    cudaGetSymbolAddress((void**)&qkv, g_qkv);
    cudaGetSymbolAddress((void**)&ctx, g_ctx);
    cudaGetSymbolAddress((void**)&tmp, g_tmp);
    cudaGetSymbolAddress((void**)&x,   g_x);
    cudaGetSymbolAddress((void**)&ff1, g_ff1);

    // 1. qkv = src @ in_proj_w^T + in_proj_b     (8192 x 3072 x 1024)
    gemm_kernel<0><<<dim3(E3 / 128, MTOK / 128), 256>>>(src, in_w, in_b, qkv,
                                                        MTOK, E3, EE);
    // 2. flash attention -> ctx (token-major, (8192,1024))
    attn_kernel<<<BB * HH * (SQ / 64), 256>>>(qkv, ctx);

    // 3. attn_out = ctx @ out_w^T + out_b        (8192 x 1024 x 1024)
    gemm_kernel<0><<<dim3(EE / 128, MTOK / 128), 256>>>(ctx, out_w, out_b, tmp,
                                                        MTOK, EE, EE);
    // 4. x = LN1(src + attn_out)
    add_ln_kernel<<<MTOK, 256>>>(src, tmp, ln1g, ln1b, x);

    // 5. ff1 = relu(x @ w1^T + b1)               (8192 x 4096 x 1024)
    gemm_kernel<1><<<dim3(DFF / 128, MTOK / 128), 256>>>(x, w1, b1, ff1,
                                                         MTOK, DFF, EE);
    // 6. ff2 = ff1 @ w2^T + b2                   (8192 x 1024 x 4096)
    gemm_kernel<0><<<dim3(EE / 128, MTOK / 128), 256>>>(ff1, w2, b2, tmp,
                                                        MTOK, EE, DFF);
    // 7. out = LN2(x + ff2)
    add_ln_kernel<<<MTOK, 256>>>(x, tmp, ln2g, ln2b, out);
}

// round 4
// speedup vs baseline: 1.5891x; 1.5891x over previous
#include <cuda_runtime.h>
#include <cuda_bf16.h>
#include <cstdint>
#include <cstddef>

// Problem constants
#define SQ   1024
#define BB   8
#define EE   1024
#define HH   16
#define DD   64
#define DFF  4096
#define MTOK (SQ * BB)     // 8192
#define E3   (3 * EE)      // 3072

// ---------------------------------------------------------------------------
// Scratch
// ---------------------------------------------------------------------------
__device__ float g_qkv[(size_t)MTOK * E3];
__device__ float g_ctx[(size_t)MTOK * EE];
__device__ float g_tmp[(size_t)MTOK * EE];
__device__ float g_x  [(size_t)MTOK * EE];
__device__ float g_ff1[(size_t)MTOK * DFF];

// ---------------------------------------------------------------------------
// helpers
// ---------------------------------------------------------------------------
__device__ __forceinline__ uint32_t smem_u32(const void* p) {
    uint32_t a;
    asm("{ .reg .u64 t; cvta.to.shared.u64 t, %1; cvt.u32.u64 %0, t; }"
        : "=r"(a) : "l"(p));
    return a;
}

__device__ __forceinline__ void ldsm4(uint32_t r[4], uint32_t addr) {
    asm volatile("ldmatrix.sync.aligned.m8n8.x4.shared.b16 {%0,%1,%2,%3}, [%4];"
                 : "=r"(r[0]), "=r"(r[1]), "=r"(r[2]), "=r"(r[3]) : "r"(addr));
}

__device__ __forceinline__ void mma16816(float c[4], const uint32_t a[4],
                                         uint32_t b0, uint32_t b1) {
    asm volatile(
        "mma.sync.aligned.m16n8k16.row.col.f32.bf16.bf16.f32 "
        "{%0,%1,%2,%3}, {%4,%5,%6,%7}, {%8,%9}, {%0,%1,%2,%3};"
        : "+f"(c[0]), "+f"(c[1]), "+f"(c[2]), "+f"(c[3])
        : "r"(a[0]), "r"(a[1]), "r"(a[2]), "r"(a[3]), "r"(b0), "r"(b1));
}

// split two floats into packed bf16x2 hi and lo words
__device__ __forceinline__ void split2(float x, float y,
                                       uint32_t& hi, uint32_t& lo) {
    __nv_bfloat16 hx = __float2bfloat16_rn(x);
    __nv_bfloat16 hy = __float2bfloat16_rn(y);
    __nv_bfloat16 lx = __float2bfloat16_rn(x - __bfloat162float(hx));
    __nv_bfloat16 ly = __float2bfloat16_rn(y - __bfloat162float(hy));
    hi = (uint32_t)__bfloat16_as_ushort(hx) |
         ((uint32_t)__bfloat16_as_ushort(hy) << 16);
    lo = (uint32_t)__bfloat16_as_ushort(lx) |
         ((uint32_t)__bfloat16_as_ushort(ly) << 16);
}

// ---------------------------------------------------------------------------
// Tensor-core GEMM via mma.sync bf16 (3-pass hi/lo): C = A[M,K] @ B[N,K]^T + bias
// CTA 128x128, BK=32, 256 threads (8 warps, warp tile 32x64).
// SMEM tiles: 128 rows x 80B stride (64B bf16 data + 16B pad) -> conflict-free
// ldmatrix. Double-buffered; global loads staged one chunk ahead in registers.
// ---------------------------------------------------------------------------
#define TSTRIDE 80
#define TILE_SZ (128 * TSTRIDE)          // 10240
#define BUF_SZ  (4 * TILE_SZ)            // Ahi,Alo,Bhi,Blo = 40960
#define GSMEM   (2 * BUF_SZ)             // 81920

template <int EPI>
__global__ __launch_bounds__(256)
void gemm_mma(const float* __restrict__ A, const float* __restrict__ Bm,
              const float* __restrict__ bias, float* __restrict__ C,
              int Ndim, int Kdim)
{
    extern __shared__ char sm[];
    const int t    = threadIdx.x;
    const int lane = t & 31;
    const int wid  = t >> 5;
    const int wm   = (wid & 3) * 32;     // warp M offset in tile
    const int wn   = (wid >> 2) * 64;    // warp N offset in tile
    const int bm   = blockIdx.y * 128;
    const int bn   = blockIdx.x * 128;

    const float* Ag = A  + (size_t)bm * Kdim;
    const float* Bg = Bm + (size_t)bn * Kdim;

    float4 stA[4], stB[4];

    auto fetch = [&](int k0) {
#pragma unroll
        for (int i = 0; i < 4; i++) {
            int e = t + i * 256;
            int r = e >> 3, c = e & 7;
            stA[i] = *(const float4*)(Ag + (size_t)r * Kdim + k0 + c * 4);
            stB[i] = *(const float4*)(Bg + (size_t)r * Kdim + k0 + c * 4);
        }
    };
    auto stash = [&](int buf) {
        char* base = sm + buf * BUF_SZ;
#pragma unroll
        for (int i = 0; i < 4; i++) {
            int e = t + i * 256;
            int r = e >> 3, c = e & 7;
            uint32_t off = (uint32_t)(r * TSTRIDE + c * 8);
            uint2 h, l;
            split2(stA[i].x, stA[i].y, h.x, l.x);
            split2(stA[i].z, stA[i].w, h.y, l.y);
            *(uint2*)(base + off)            = h;   // A hi
            *(uint2*)(base + TILE_SZ + off)  = l;   // A lo
            split2(stB[i].x, stB[i].y, h.x, l.x);
            split2(stB[i].z, stB[i].w, h.y, l.y);
            *(uint2*)(base + 2 * TILE_SZ + off) = h; // B hi
            *(uint2*)(base + 3 * TILE_SZ + off) = l; // B lo
        }
    };

    float acc[2][8][4];
#pragma unroll
    for (int i = 0; i < 2; i++)
#pragma unroll
        for (int j = 0; j < 8; j++)
#pragma unroll
            for (int k = 0; k < 4; k++) acc[i][j][k] = 0.0f;

    const int kc = Kdim / 32;
    fetch(0);
    stash(0);
    __syncthreads();

    for (int ic = 0; ic < kc; ic++) {
        const int buf = ic & 1;
        if (ic + 1 < kc) fetch((ic + 1) * 32);

        const uint32_t sb  = smem_u32(sm) + buf * BUF_SZ;
        const uint32_t pAh = sb;
        const uint32_t pAl = sb + TILE_SZ;
        const uint32_t pBh = sb + 2 * TILE_SZ;
        const uint32_t pBl = sb + 3 * TILE_SZ;

#pragma unroll
        for (int ks = 0; ks < 2; ks++) {
            // A fragments: two m16 tiles, hi and lo
            uint32_t Ah[2][4], Al[2][4];
#pragma unroll
            for (int i = 0; i < 2; i++) {
                uint32_t off = (uint32_t)((wm + i * 16 + (lane & 15)) * TSTRIDE
                               + ks * 32 + ((lane >> 4) << 4));
                ldsm4(Ah[i], pAh + off);
                ldsm4(Al[i], pAl + off);
            }
#pragma unroll
            for (int bh2 = 0; bh2 < 2; bh2++) {          // two n32 halves
                uint32_t Bf[2][4];
                uint32_t boff[2];
#pragma unroll
                for (int g = 0; g < 2; g++) {            // n16 groups
                    int nb = wn + bh2 * 32 + g * 16;
                    uint32_t off = (uint32_t)((nb + (lane & 7) + ((lane >> 4) << 3)) * TSTRIDE
                                   + ks * 32 + (((lane >> 3) & 1) << 4));
                    boff[g] = off;
                    ldsm4(Bf[g], pBh + off);
                }
                // hh + lh passes
#pragma unroll
                for (int g = 0; g < 2; g++)
#pragma unroll
                    for (int jj = 0; jj < 2; jj++) {
                        int j = bh2 * 4 + g * 2 + jj;
                        uint32_t b0 = Bf[g][jj * 2], b1 = Bf[g][jj * 2 + 1];
#pragma unroll
                        for (int i = 0; i < 2; i++) {
                            mma16816(acc[i][j], Ah[i], b0, b1);
                            mma16816(acc[i][j], Al[i], b0, b1);
                        }
                    }
                // hl pass (reload B as lo)
#pragma unroll
                for (int g = 0; g < 2; g++) ldsm4(Bf[g], pBl + boff[g]);
#pragma unroll
                for (int g = 0; g < 2; g++)
#pragma unroll
                    for (int jj = 0; jj < 2; jj++) {
                        int j = bh2 * 4 + g * 2 + jj;
#pragma unroll
                        for (int i = 0; i < 2; i++)
                            mma16816(acc[i][j], Ah[i], Bf[g][jj * 2], Bf[g][jj * 2 + 1]);
                    }
            }
        }
        if (ic + 1 < kc) stash(buf ^ 1);
        __syncthreads();
    }

    // epilogue
#pragma unroll
    for (int i = 0; i < 2; i++) {
        const int r0 = bm + wm + i * 16 + (lane >> 2);
#pragma unroll
        for (int j = 0; j < 8; j++) {
            const int c = bn + wn + j * 8 + 2 * (lane & 3);
            const float bx = bias[c], by = bias[c + 1];
            float2 v0 = {acc[i][j][0] + bx, acc[i][j][1] + by};
            float2 v1 = {acc[i][j][2] + bx, acc[i][j][3] + by};
            if (EPI == 1) {
                v0.x = fmaxf(v0.x, 0.f); v0.y = fmaxf(v0.y, 0.f);
                v1.x = fmaxf(v1.x, 0.f); v1.y = fmaxf(v1.y, 0.f);
            }
            *(float2*)(C + (size_t)r0 * Ndim + c)       = v0;
            *(float2*)(C + (size_t)(r0 + 8) * Ndim + c) = v1;
        }
    }
}

// ---------------------------------------------------------------------------
// Flash attention, fp32 SIMT (unchanged)
// ---------------------------------------------------------------------------
__global__ __launch_bounds__(256)
void attn_kernel(const float* __restrict__ qkv, float* __restrict__ ctx)
{
    __shared__ float Qs[64][64];
    __shared__ float Ks[32][65];
    __shared__ float Vs[32][64];
    __shared__ float Ps[64][33];

    const int qt = blockIdx.x & 15;
    const int bh = blockIdx.x >> 4;
    const int b  = bh / HH;
    const int h  = bh % HH;

    const int t = threadIdx.x;
    const int r = t >> 2;
    const int q = t & 3;

    const size_t rowstride = (size_t)BB * E3;
    const float* Qg = qkv + ((size_t)(qt * 64) * BB + b) * E3 + h * DD;
    const float* Kg = qkv + (size_t)b * E3 + EE + h * DD;
    const float* Vg = Kg + EE;

#pragma unroll
    for (int i = 0; i < 16; i++) {
        int e = t + i * 256;
        int row = e >> 6, col = e & 63;
        Qs[row][col] = Qg[(size_t)row * rowstride + col] * 0.125f;
    }

    float o[16];
#pragma unroll
    for (int dd = 0; dd < 16; dd++) o[dd] = 0.0f;
    float m_i = -1e30f, l_i = 0.0f;

    __syncthreads();

    for (int kt = 0; kt < SQ / 32; kt++) {
#pragma unroll
        for (int i = 0; i < 8; i++) {
            int e = t + i * 256;
            int row = e >> 6, col = e & 63;
            size_t goff = (size_t)(kt * 32 + row) * rowstride + col;
            Ks[row][col] = Kg[goff];
            Vs[row][col] = Vg[goff];
        }
        __syncthreads();

        float sacc[8] = {0, 0, 0, 0, 0, 0, 0, 0};
        const int kb = q * 8;
#pragma unroll 8
        for (int d = 0; d < 64; d++) {
            float qd = Qs[r][d];
#pragma unroll
            for (int j = 0; j < 8; j++)
                sacc[j] = fmaf(qd, Ks[kb + j][d], sacc[j]);
        }

        float tmax = sacc[0];
#pragma unroll
        for (int j = 1; j < 8; j++) tmax = fmaxf(tmax, sacc[j]);
        tmax = fmaxf(tmax, __shfl_xor_sync(0xffffffffu, tmax, 1));
        tmax = fmaxf(tmax, __shfl_xor_sync(0xffffffffu, tmax, 2));

        float new_m = fmaxf(m_i, tmax);
        float corr  = __expf(m_i - new_m);

        float tsum = 0.0f;
        float p[8];
#pragma unroll
        for (int j = 0; j < 8; j++) {
            p[j] = __expf(sacc[j] - new_m);
            tsum += p[j];
        }
        tsum += __shfl_xor_sync(0xffffffffu, tsum, 1);
        tsum += __shfl_xor_sync(0xffffffffu, tsum, 2);

        l_i = l_i * corr + tsum;
        m_i = new_m;
#pragma unroll
        for (int dd = 0; dd < 16; dd++) o[dd] *= corr;
#pragma unroll
        for (int j = 0; j < 8; j++) Ps[r][kb + j] = p[j];
        __syncthreads();

#pragma unroll 4
        for (int k = 0; k < 32; k++) {
            float pv = Ps[r][k];
#pragma unroll
            for (int dd = 0; dd < 16; dd++)
                o[dd] = fmaf(pv, Vs[k][q + dd * 4], o[dd]);
        }
        __syncthreads();
    }

    float inv_l = 1.0f / l_i;
    const int srow = qt * 64 + r;
    float* Cp = ctx + ((size_t)srow * BB + b) * EE + h * DD;
#pragma unroll
    for (int dd = 0; dd < 16; dd++)
        Cp[q + dd * 4] = o[dd] * inv_l;
}

// ---------------------------------------------------------------------------
// out = layernorm(a + b) * g + beta
// ---------------------------------------------------------------------------
__global__ __launch_bounds__(256)
void add_ln_kernel(const float* __restrict__ a, const float* __restrict__ bres,
                   const float* __restrict__ g, const float* __restrict__ beta,
                   float* __restrict__ out)
{
    const int row = blockIdx.x;
    const int t   = threadIdx.x;
    const float4* A4 = (const float4*)(a    + (size_t)row * EE);
    const float4* B4 = (const float4*)(bres + (size_t)row * EE);

    float4 x = A4[t];
    float4 y = B4[t];
    x.x += y.x; x.y += y.y; x.z += y.z; x.w += y.w;

    float s  = x.x + x.y + x.z + x.w;
    float ss = x.x * x.x + x.y * x.y + x.z * x.z + x.w * x.w;

#pragma unroll
    for (int off = 16; off > 0; off >>= 1) {
        s  += __shfl_xor_sync(0xffffffffu, s,  off);
        ss += __shfl_xor_sync(0xffffffffu, ss, off);
    }
    __shared__ float sh_s[8], sh_ss[8];
    const int w = t >> 5, l = t & 31;
    if (l == 0) { sh_s[w] = s; sh_ss[w] = ss; }
    __syncthreads();
    s = 0.0f; ss = 0.0f;
#pragma unroll
    for (int i = 0; i < 8; i++) { s += sh_s[i]; ss += sh_ss[i]; }

    const float mean = s * (1.0f / EE);
    const float var  = ss * (1.0f / EE) - mean * mean;
    const float rstd = rsqrtf(var + 1e-5f);

    float4 g4 = ((const float4*)g)[t];
    float4 b4 = ((const float4*)beta)[t];
    float4 o;
    o.x = (x.x - mean) * rstd * g4.x + b4.x;
    o.y = (x.y - mean) * rstd * g4.y + b4.y;
    o.z = (x.z - mean) * rstd * g4.z + b4.z;
    o.w = (x.w - mean) * rstd * g4.w + b4.w;
    ((float4*)(out + (size_t)row * EE))[t] = o;
}

// ---------------------------------------------------------------------------
// launch
// ---------------------------------------------------------------------------
extern "C" void kernel_launch(void* const* d_in, const int* in_sizes, int n_in,
                              void* d_out, int out_size)
{
    const float* src    = (const float*)d_in[0];
    const float* in_w   = (const float*)d_in[1];
    const float* in_b   = (const float*)d_in[2];
    const float* out_w  = (const float*)d_in[3];
    const float* out_b  = (const float*)d_in[4];
    const float* ln1g   = (const float*)d_in[5];
    const float* ln1b   = (const float*)d_in[6];
    const float* ln2g   = (const float*)d_in[7];
    const float* ln2b   = (const float*)d_in[8];
    const float* w1     = (const float*)d_in[9];
    const float* b1     = (const float*)d_in[10];
    const float* w2     = (const float*)d_in[11];
    const float* b2     = (const float*)d_in[12];
    float* out = (float*)d_out;

    float *qkv, *ctx, *tmp, *x, *ff1;
    cudaGetSymbolAddress((void**)&qkv, g_qkv);
    cudaGetSymbolAddress((void**)&ctx, g_ctx);
    cudaGetSymbolAddress((void**)&tmp, g_tmp);
    cudaGetSymbolAddress((void**)&x,   g_x);
    cudaGetSymbolAddress((void**)&ff1, g_ff1);

    cudaFuncSetAttribute(gemm_mma<0>, cudaFuncAttributeMaxDynamicSharedMemorySize, GSMEM);
    cudaFuncSetAttribute(gemm_mma<1>, cudaFuncAttributeMaxDynamicSharedMemorySize, GSMEM);

    // 1. qkv = src @ in_proj_w^T + b           (8192 x 3072 x 1024)
    gemm_mma<0><<<dim3(E3 / 128, MTOK / 128), 256, GSMEM>>>(src, in_w, in_b, qkv, E3, EE);
    // 2. flash attention
    attn_kernel<<<BB * HH * (SQ / 64), 256>>>(qkv, ctx);
    // 3. attn_out = ctx @ out_w^T + out_b      (8192 x 1024 x 1024)
    gemm_mma<0><<<dim3(EE / 128, MTOK / 128), 256, GSMEM>>>(ctx, out_w, out_b, tmp, EE, EE);
    // 4. x = LN1(src + attn_out)
    add_ln_kernel<<<MTOK, 256>>>(src, tmp, ln1g, ln1b, x);
    // 5. ff1 = relu(x @ w1^T + b1)             (8192 x 4096 x 1024)
    gemm_mma<1><<<dim3(DFF / 128, MTOK / 128), 256, GSMEM>>>(x, w1, b1, ff1, DFF, EE);
    // 6. ff2 = ff1 @ w2^T + b2                 (8192 x 1024 x 4096)
    gemm_mma<0><<<dim3(EE / 128, MTOK / 128), 256, GSMEM>>>(ff1, w2, b2, tmp, EE, DFF);
    // 7. out = LN2(x + ff2)
    add_ln_kernel<<<MTOK, 256>>>(x, tmp, ln2g, ln2b, out);
}

// round 8
// speedup vs baseline: 1.8767x; 1.1810x over previous
#include <cuda_runtime.h>
#include <cuda_bf16.h>
#include <cstdint>
#include <cstddef>

// Problem constants
#define SQ   1024
#define BB   8
#define EE   1024
#define HH   16
#define DD   64
#define DFF  4096
#define MTOK (SQ * BB)     // 8192
#define E3   (3 * EE)      // 3072

// ---------------------------------------------------------------------------
// Scratch (__device__ globals; no allocations allowed)
// ---------------------------------------------------------------------------
__device__ float g_qkv[(size_t)MTOK * E3];
__device__ float g_tmp[(size_t)MTOK * EE];
__device__ float g_x  [(size_t)MTOK * EE];

__device__ __nv_bfloat16 g_srch[(size_t)MTOK * EE],  g_srcl[(size_t)MTOK * EE];
__device__ __nv_bfloat16 g_ctxh[(size_t)MTOK * EE],  g_ctxl[(size_t)MTOK * EE];
__device__ __nv_bfloat16 g_xh  [(size_t)MTOK * EE],  g_xl  [(size_t)MTOK * EE];
__device__ __nv_bfloat16 g_ff1h[(size_t)MTOK * DFF], g_ff1l[(size_t)MTOK * DFF];

__device__ __nv_bfloat16 g_inwh[(size_t)E3 * EE],  g_inwl[(size_t)E3 * EE];
__device__ __nv_bfloat16 g_outwh[(size_t)EE * EE], g_outwl[(size_t)EE * EE];
__device__ __nv_bfloat16 g_w1h[(size_t)DFF * EE],  g_w1l[(size_t)DFF * EE];
__device__ __nv_bfloat16 g_w2h[(size_t)EE * DFF],  g_w2l[(size_t)EE * DFF];

// ---------------------------------------------------------------------------
// helpers
// ---------------------------------------------------------------------------
__device__ __forceinline__ uint32_t smem_u32(const void* p) {
    uint32_t a;
    asm("{ .reg .u64 t; cvta.to.shared.u64 t, %1; cvt.u32.u64 %0, t; }"
        : "=r"(a) : "l"(p));
    return a;
}
__device__ __forceinline__ void cpasync16(uint32_t s, const void* g) {
    asm volatile("cp.async.cg.shared.global [%0], [%1], 16;" :: "r"(s), "l"(g));
}
__device__ __forceinline__ void ldsm4(uint32_t r[4], uint32_t addr) {
    asm volatile("ldmatrix.sync.aligned.m8n8.x4.shared.b16 {%0,%1,%2,%3}, [%4];"
                 : "=r"(r[0]), "=r"(r[1]), "=r"(r[2]), "=r"(r[3]) : "r"(addr));
}
__device__ __forceinline__ void mma16816(float c[4], const uint32_t a[4],
                                         uint32_t b0, uint32_t b1) {
    asm volatile(
        "mma.sync.aligned.m16n8k16.row.col.f32.bf16.bf16.f32 "
        "{%0,%1,%2,%3}, {%4,%5,%6,%7}, {%8,%9}, {%0,%1,%2,%3};"
        : "+f"(c[0]), "+f"(c[1]), "+f"(c[2]), "+f"(c[3])
        : "r"(a[0]), "r"(a[1]), "r"(a[2]), "r"(a[3]), "r"(b0), "r"(b1));
}
__device__ __forceinline__ uint32_t pack_bf2(float x, float y) {
    __nv_bfloat16 bx = __float2bfloat16_rn(x);
    __nv_bfloat16 by = __float2bfloat16_rn(y);
    return (uint32_t)__bfloat16_as_ushort(bx) |
           ((uint32_t)__bfloat16_as_ushort(by) << 16);
}
// write hi/lo split of pair (x,y) to H[idx],H[idx+1] / L[idx],L[idx+1]
__device__ __forceinline__ void store_split2(__nv_bfloat16* H, __nv_bfloat16* L,
                                             size_t idx, float x, float y) {
    __nv_bfloat16 hx = __float2bfloat16_rn(x);
    __nv_bfloat16 hy = __float2bfloat16_rn(y);
    *(uint32_t*)(H + idx) = (uint32_t)__bfloat16_as_ushort(hx) |
                            ((uint32_t)__bfloat16_as_ushort(hy) << 16);
    *(uint32_t*)(L + idx) = pack_bf2(x - __bfloat162float(hx),
                                     y - __bfloat162float(hy));
}

// ---------------------------------------------------------------------------
// fp32 -> bf16 hi/lo split (one-time per launch for weights / src)
// ---------------------------------------------------------------------------
__global__ __launch_bounds__(256)
void split_kernel(const float* __restrict__ in, __nv_bfloat16* __restrict__ hi,
                  __nv_bfloat16* __restrict__ lo, int n4)
{
    int i = blockIdx.x * blockDim.x + threadIdx.x;
    if (i >= n4) return;
    float4 v = ((const float4*)in)[i];
    __nv_bfloat16 h0 = __float2bfloat16_rn(v.x);
    __nv_bfloat16 h1 = __float2bfloat16_rn(v.y);
    __nv_bfloat16 h2 = __float2bfloat16_rn(v.z);
    __nv_bfloat16 h3 = __float2bfloat16_rn(v.w);
    uint2 hp, lp;
    hp.x = (uint32_t)__bfloat16_as_ushort(h0) | ((uint32_t)__bfloat16_as_ushort(h1) << 16);
    hp.y = (uint32_t)__bfloat16_as_ushort(h2) | ((uint32_t)__bfloat16_as_ushort(h3) << 16);
    lp.x = pack_bf2(v.x - __bfloat162float(h0), v.y - __bfloat162float(h1));
    lp.y = pack_bf2(v.z - __bfloat162float(h2), v.w - __bfloat162float(h3));
    ((uint2*)hi)[i] = hp;
    ((uint2*)lo)[i] = lp;
}

// ---------------------------------------------------------------------------
// Tensor-core GEMM, pre-split bf16 hi/lo operands (3-pass):
//   C = A[M,K] @ B[N,K]^T + bias
// CTA 128x128, BK=32, 256 threads (8 warps, warp tile 32x64).
// cp.async 2-stage pipeline; smem rows 64B data + 16B pad (80B stride).
// EPI: 0 = bias -> fp32 C;  1 = bias+relu -> bf16 hi/lo planes (Ch, Cl).
// ---------------------------------------------------------------------------
#define TSTRIDE 80
#define PLANE   (128 * TSTRIDE)          // 10240 B
#define STAGE   (4 * PLANE)              // Ah,Al,Bh,Bl = 40960 B
#define GSMEM   (2 * STAGE)              // 81920 B

template <int EPI>
__global__ __launch_bounds__(256, 2)
void gemm_mma(const __nv_bfloat16* __restrict__ Agh, const __nv_bfloat16* __restrict__ Agl,
              const __nv_bfloat16* __restrict__ Bgh, const __nv_bfloat16* __restrict__ Bgl,
              const float* __restrict__ bias,
              float* __restrict__ C,
              __nv_bfloat16* __restrict__ Ch, __nv_bfloat16* __restrict__ Cl,
              int Ndim, int Kdim)
{
    extern __shared__ char sm[];
    const int t    = threadIdx.x;
    const int lane = t & 31;
    const int wid  = t >> 5;
    const int wm   = (wid & 3) * 32;
    const int wn   = (wid >> 2) * 64;
    const int bm   = blockIdx.y * 128;
    const int bn   = blockIdx.x * 128;

    const uint32_t smb = smem_u32(sm);

    auto issue = [&](int k0, int buf) {
        uint32_t sb = smb + buf * STAGE;
#pragma unroll
        for (int i = 0; i < 2; i++) {
            int e = t + i * 256;                  // 0..511
            int r = e >> 2, c = e & 3;
            uint32_t off = (uint32_t)(r * TSTRIDE + c * 16);
            size_t ga = (size_t)(bm + r) * Kdim + k0 + c * 8;
            size_t gb = (size_t)(bn + r) * Kdim + k0 + c * 8;
            cpasync16(sb + off,             Agh + ga);
            cpasync16(sb + PLANE + off,     Agl + ga);
            cpasync16(sb + 2 * PLANE + off, Bgh + gb);
            cpasync16(sb + 3 * PLANE + off, Bgl + gb);
        }
        asm volatile("cp.async.commit_group;");
    };

    float acc[2][8][4];
#pragma unroll
    for (int i = 0; i < 2; i++)
#pragma unroll
        for (int j = 0; j < 8; j++)
#pragma unroll
            for (int k = 0; k < 4; k++) acc[i][j][k] = 0.0f;

    const int kc = Kdim / 32;
    issue(0, 0);

    for (int ic = 0; ic < kc; ic++) {
        const int buf = ic & 1;
        if (ic + 1 < kc) {
            issue((ic + 1) * 32, buf ^ 1);
            asm volatile("cp.async.wait_group 1;");
        } else {
            asm volatile("cp.async.wait_group 0;");
        }
        __syncthreads();

        const uint32_t pAh = smb + buf * STAGE;
        const uint32_t pAl = pAh + PLANE;
        const uint32_t pBh = pAh + 2 * PLANE;
        const uint32_t pBl = pAh + 3 * PLANE;

#pragma unroll
        for (int ks = 0; ks < 2; ks++) {
            uint32_t Ah[2][4], Al[2][4];
#pragma unroll
            for (int i = 0; i < 2; i++) {
                uint32_t off = (uint32_t)((wm + i * 16 + (lane & 15)) * TSTRIDE
                               + ks * 32 + ((lane >> 4) << 4));
                ldsm4(Ah[i], pAh + off);
                ldsm4(Al[i], pAl + off);
            }
#pragma unroll
            for (int bh2 = 0; bh2 < 2; bh2++) {
                uint32_t Bf[2][4];
                uint32_t boff[2];
#pragma unroll
                for (int g = 0; g < 2; g++) {
                    int nb = wn + bh2 * 32 + g * 16;
                    uint32_t off = (uint32_t)((nb + (lane & 7) + ((lane >> 4) << 3)) * TSTRIDE
                                   + ks * 32 + (((lane >> 3) & 1) << 4));
                    boff[g] = off;
                    ldsm4(Bf[g], pBh + off);
                }
#pragma unroll
                for (int g = 0; g < 2; g++)
#pragma unroll
                    for (int jj = 0; jj < 2; jj++) {
                        int j = bh2 * 4 + g * 2 + jj;
                        uint32_t b0 = Bf[g][jj * 2], b1 = Bf[g][jj * 2 + 1];
#pragma unroll
                        for (int i = 0; i < 2; i++) {
                            mma16816(acc[i][j], Ah[i], b0, b1);
                            mma16816(acc[i][j], Al[i], b0, b1);
                        }
                    }
#pragma unroll
                for (int g = 0; g < 2; g++) ldsm4(Bf[g], pBl + boff[g]);
#pragma unroll
                for (int g = 0; g < 2; g++)
#pragma unroll
                    for (int jj = 0; jj < 2; jj++) {
                        int j = bh2 * 4 + g * 2 + jj;
#pragma unroll
                        for (int i = 0; i < 2; i++)
                            mma16816(acc[i][j], Ah[i], Bf[g][jj * 2], Bf[g][jj * 2 + 1]);
                    }
            }
        }
        __syncthreads();
    }

    // epilogue
#pragma unroll
    for (int i = 0; i < 2; i++) {
        const int r0 = bm + wm + i * 16 + (lane >> 2);
#pragma unroll
        for (int j = 0; j < 8; j++) {
            const int c = bn + wn + j * 8 + 2 * (lane & 3);
            const float bx = bias[c], by = bias[c + 1];
            float v0x = acc[i][j][0] + bx, v0y = acc[i][j][1] + by;
            float v1x = acc[i][j][2] + bx, v1y = acc[i][j][3] + by;
            if (EPI == 0) {
                *(float2*)(C + (size_t)r0 * Ndim + c)       = make_float2(v0x, v0y);
                *(float2*)(C + (size_t)(r0 + 8) * Ndim + c) = make_float2(v1x, v1y);
            } else {
                v0x = fmaxf(v0x, 0.f); v0y = fmaxf(v0y, 0.f);
                v1x = fmaxf(v1x, 0.f); v1y = fmaxf(v1y, 0.f);
                store_split2(Ch, Cl, (size_t)r0 * Ndim + c, v0x, v0y);
                store_split2(Ch, Cl, (size_t)(r0 + 8) * Ndim + c, v1x, v1y);
            }
        }
    }
}

// ---------------------------------------------------------------------------
// Flash attention, fp32 SIMT; output written as bf16 hi/lo planes
// ---------------------------------------------------------------------------
__global__ __launch_bounds__(256)
void attn_kernel(const float* __restrict__ qkv,
                 __nv_bfloat16* __restrict__ ctxh, __nv_bfloat16* __restrict__ ctxl)
{
    __shared__ float Qs[64][64];
    __shared__ float Ks[32][65];
    __shared__ float Vs[32][64];
    __shared__ float Ps[64][33];

    const int qt = blockIdx.x & 15;
    const int bh = blockIdx.x >> 4;
    const int b  = bh / HH;
    const int h  = bh % HH;

    const int t = threadIdx.x;
    const int r = t >> 2;
    const int q = t & 3;

    const size_t rowstride = (size_t)BB * E3;
    const float* Qg = qkv + ((size_t)(qt * 64) * BB + b) * E3 + h * DD;
    const float* Kg = qkv + (size_t)b * E3 + EE + h * DD;
    const float* Vg = Kg + EE;

#pragma unroll
    for (int i = 0; i < 16; i++) {
        int e = t + i * 256;
        int row = e >> 6, col = e & 63;
        Qs[row][col] = Qg[(size_t)row * rowstride + col] * 0.125f;
    }

    float o[16];
#pragma unroll
    for (int dd = 0; dd < 16; dd++) o[dd] = 0.0f;
    float m_i = -1e30f, l_i = 0.0f;

    __syncthreads();

    for (int kt = 0; kt < SQ / 32; kt++) {
#pragma unroll
        for (int i = 0; i < 8; i++) {
            int e = t + i * 256;
            int row = e >> 6, col = e & 63;
            size_t goff = (size_t)(kt * 32 + row) * rowstride + col;
            Ks[row][col] = Kg[goff];
            Vs[row][col] = Vg[goff];
        }
        __syncthreads();

        float sacc[8] = {0, 0, 0, 0, 0, 0, 0, 0};
        const int kb = q * 8;
#pragma unroll 8
        for (int d = 0; d < 64; d++) {
            float qd = Qs[r][d];
#pragma unroll
            for (int j = 0; j < 8; j++)
                sacc[j] = fmaf(qd, Ks[kb + j][d], sacc[j]);
        }

        float tmax = sacc[0];
#pragma unroll
        for (int j = 1; j < 8; j++) tmax = fmaxf(tmax, sacc[j]);
        tmax = fmaxf(tmax, __shfl_xor_sync(0xffffffffu, tmax, 1));
        tmax = fmaxf(tmax, __shfl_xor_sync(0xffffffffu, tmax, 2));

        float new_m = fmaxf(m_i, tmax);
        float corr  = __expf(m_i - new_m);

        float tsum = 0.0f;
        float p[8];
#pragma unroll
        for (int j = 0; j < 8; j++) {
            p[j] = __expf(sacc[j] - new_m);
            tsum += p[j];
        }
        tsum += __shfl_xor_sync(0xffffffffu, tsum, 1);
        tsum += __shfl_xor_sync(0xffffffffu, tsum, 2);

        l_i = l_i * corr + tsum;
        m_i = new_m;
#pragma unroll
        for (int dd = 0; dd < 16; dd++) o[dd] *= corr;
#pragma unroll
        for (int j = 0; j < 8; j++) Ps[r][kb + j] = p[j];
        __syncthreads();

#pragma unroll 4
        for (int k = 0; k < 32; k++) {
            float pv = Ps[r][k];
#pragma unroll
            for (int dd = 0; dd < 16; dd++)
                o[dd] = fmaf(pv, Vs[k][q + dd * 4], o[dd]);
        }
        __syncthreads();
    }

    float inv_l = 1.0f / l_i;
    const int srow = qt * 64 + r;
    const size_t obase = ((size_t)srow * BB + b) * EE + h * DD;
#pragma unroll
    for (int dd = 0; dd < 16; dd++) {
        float v = o[dd] * inv_l;
        __nv_bfloat16 hv = __float2bfloat16_rn(v);
        ctxh[obase + q + dd * 4] = hv;
        ctxl[obase + q + dd * 4] = __float2bfloat16_rn(v - __bfloat162float(hv));
    }
}

// ---------------------------------------------------------------------------
// out = layernorm(a + b) * g + beta; SPLIT=1 also writes bf16 hi/lo planes
// ---------------------------------------------------------------------------
template <int SPLIT>
__global__ __launch_bounds__(256)
void add_ln_kernel(const float* __restrict__ a, const float* __restrict__ bres,
                   const float* __restrict__ g, const float* __restrict__ beta,
                   float* __restrict__ out,
                   __nv_bfloat16* __restrict__ oh, __nv_bfloat16* __restrict__ ol)
{
    const int row = blockIdx.x;
    const int t   = threadIdx.x;
    const float4* A4 = (const float4*)(a    + (size_t)row * EE);
    const float4* B4 = (const float4*)(bres + (size_t)row * EE);

    float4 x = A4[t];
    float4 y = B4[t];
    x.x += y.x; x.y += y.y; x.z += y.z; x.w += y.w;

    float s  = x.x + x.y + x.z + x.w;
    float ss = x.x * x.x + x.y * x.y + x.z * x.z + x.w * x.w;

#pragma unroll
    for (int off = 16; off > 0; off >>= 1) {
        s  += __shfl_xor_sync(0xffffffffu, s,  off);
        ss += __shfl_xor_sync(0xffffffffu, ss, off);
    }
    __shared__ float sh_s[8], sh_ss[8];
    const int w = t >> 5, l = t & 31;
    if (l == 0) { sh_s[w] = s; sh_ss[w] = ss; }
    __syncthreads();
    s = 0.0f; ss = 0.0f;
#pragma unroll
    for (int i = 0; i < 8; i++) { s += sh_s[i]; ss += sh_ss[i]; }

    const float mean = s * (1.0f / EE);
    const float var  = ss * (1.0f / EE) - mean * mean;
    const float rstd = rsqrtf(var + 1e-5f);

    float4 g4 = ((const float4*)g)[t];
    float4 b4 = ((const float4*)beta)[t];
    float4 o;
    o.x = (x.x - mean) * rstd * g4.x + b4.x;
    o.y = (x.y - mean) * rstd * g4.y + b4.y;
    o.z = (x.z - mean) * rstd * g4.z + b4.z;
    o.w = (x.w - mean) * rstd * g4.w + b4.w;
    ((float4*)(out + (size_t)row * EE))[t] = o;

    if (SPLIT) {
        size_t idx = (size_t)row * EE + t * 4;
        store_split2(oh, ol, idx,     o.x, o.y);
        store_split2(oh, ol, idx + 2, o.z, o.w);
    }
}

// ---------------------------------------------------------------------------
// launch
// ---------------------------------------------------------------------------
extern "C" void kernel_launch(void* const* d_in, const int* in_sizes, int n_in,
                              void* d_out, int out_size)
{
    const float* src    = (const float*)d_in[0];
    const float* in_w   = (const float*)d_in[1];
    const float* in_b   = (const float*)d_in[2];
    const float* out_w  = (const float*)d_in[3];
    const float* out_b  = (const float*)d_in[4];
    const float* ln1g   = (const float*)d_in[5];
    const float* ln1b   = (const float*)d_in[6];
    const float* ln2g   = (const float*)d_in[7];
    const float* ln2b   = (const float*)d_in[8];
    const float* w1     = (const float*)d_in[9];
    const float* b1     = (const float*)d_in[10];
    const float* w2     = (const float*)d_in[11];
    const float* b2     = (const float*)d_in[12];
    float* out = (float*)d_out;

    float *qkv, *tmp, *x;
    cudaGetSymbolAddress((void**)&qkv, g_qkv);
    cudaGetSymbolAddress((void**)&tmp, g_tmp);
    cudaGetSymbolAddress((void**)&x,   g_x);

    __nv_bfloat16 *srch, *srcl, *ctxh, *ctxl, *xh, *xl, *ff1h, *ff1l;
    __nv_bfloat16 *inwh, *inwl, *outwh, *outwl, *w1h, *w1l, *w2h, *w2l;
    cudaGetSymbolAddress((void**)&srch, g_srch);  cudaGetSymbolAddress((void**)&srcl, g_srcl);
    cudaGetSymbolAddress((void**)&ctxh, g_ctxh);  cudaGetSymbolAddress((void**)&ctxl, g_ctxl);
    cudaGetSymbolAddress((void**)&xh,   g_xh);    cudaGetSymbolAddress((void**)&xl,   g_xl);
    cudaGetSymbolAddress((void**)&ff1h, g_ff1h);  cudaGetSymbolAddress((void**)&ff1l, g_ff1l);
    cudaGetSymbolAddress((void**)&inwh, g_inwh);  cudaGetSymbolAddress((void**)&inwl, g_inwl);
    cudaGetSymbolAddress((void**)&outwh, g_outwh);cudaGetSymbolAddress((void**)&outwl, g_outwl);
    cudaGetSymbolAddress((void**)&w1h,  g_w1h);   cudaGetSymbolAddress((void**)&w1l,  g_w1l);
    cudaGetSymbolAddress((void**)&w2h,  g_w2h);   cudaGetSymbolAddress((void**)&w2l,  g_w2l);

    cudaFuncSetAttribute(gemm_mma<0>, cudaFuncAttributeMaxDynamicSharedMemorySize, GSMEM);
    cudaFuncSetAttribute(gemm_mma<1>, cudaFuncAttributeMaxDynamicSharedMemorySize, GSMEM);

    // 0. one-time splits (weights + src)
    auto splits = [&](const float* p, __nv_bfloat16* h, __nv_bfloat16* l, size_t n) {
        int n4 = (int)(n / 4);
        split_kernel<<<(n4 + 255) / 256, 256>>>(p, h, l, n4);
    };
    splits(in_w,  inwh,  inwl,  (size_t)E3 * EE);
    splits(out_w, outwh, outwl, (size_t)EE * EE);
    splits(w1,    w1h,   w1l,   (size_t)DFF * EE);
    splits(w2,    w2h,   w2l,   (size_t)EE * DFF);
    splits(src,   srch,  srcl,  (size_t)MTOK * EE);

    // 1. qkv = src @ in_proj_w^T + b        (8192 x 3072 x 1024) -> fp32
    gemm_mma<0><<<dim3(E3 / 128, MTOK / 128), 256, GSMEM>>>(
        srch, srcl, inwh, inwl, in_b, qkv, nullptr, nullptr, E3, EE);
    // 2. flash attention -> ctx bf16 hi/lo
    attn_kernel<<<BB * HH * (SQ / 64), 256>>>(qkv, ctxh, ctxl);
    // 3. attn_out = ctx @ out_w^T + out_b   (8192 x 1024 x 1024) -> fp32 tmp
    gemm_mma<0><<<dim3(EE / 128, MTOK / 128), 256, GSMEM>>>(
        ctxh, ctxl, outwh, outwl, out_b, tmp, nullptr, nullptr, EE, EE);
    // 4. x = LN1(src + attn_out) -> fp32 x + bf16 planes
    add_ln_kernel<1><<<MTOK, 256>>>(src, tmp, ln1g, ln1b, x, xh, xl);
    // 5. ff1 = relu(x @ w1^T + b1)          (8192 x 4096 x 1024) -> bf16 planes
    gemm_mma<1><<<dim3(DFF / 128, MTOK / 128), 256, GSMEM>>>(
        xh, xl, w1h, w1l, b1, nullptr, ff1h, ff1l, DFF, EE);
    // 6. ff2 = ff1 @ w2^T + b2              (8192 x 1024 x 4096) -> fp32 tmp
    gemm_mma<0><<<dim3(EE / 128, MTOK / 128), 256, GSMEM>>>(
        ff1h, ff1l, w2h, w2l, b2, tmp, nullptr, nullptr, EE, DFF);
    // 7. out = LN2(x + ff2)
    add_ln_kernel<0><<<MTOK, 256>>>(x, tmp, ln2g, ln2b, out, nullptr, nullptr);
}

// round 9
// speedup vs baseline: 2.1207x; 1.1301x over previous
#include <cuda_runtime.h>
#include <cuda_fp16.h>
#include <cstdint>
#include <cstddef>

// Problem constants
#define SQ   1024
#define BB   8
#define EE   1024
#define HH   16
#define DD   64
#define DFF  4096
#define MTOK (SQ * BB)     // 8192
#define E3   (3 * EE)      // 3072

// ---------------------------------------------------------------------------
// Scratch (__device__ globals; no allocations allowed)
// ---------------------------------------------------------------------------
__device__ float g_qkv[(size_t)MTOK * E3];
__device__ float g_tmp[(size_t)MTOK * EE];
__device__ float g_x  [(size_t)MTOK * EE];

// fp16 single-plane activations
__device__ __half g_src16[(size_t)MTOK * EE];
__device__ __half g_ctx16[(size_t)MTOK * EE];
__device__ __half g_x16  [(size_t)MTOK * EE];
__device__ __half g_ff116[(size_t)MTOK * DFF];

// fp16 hi/lo weight planes
__device__ __half g_inwh[(size_t)E3 * EE],  g_inwl[(size_t)E3 * EE];
__device__ __half g_outwh[(size_t)EE * EE], g_outwl[(size_t)EE * EE];
__device__ __half g_w1h[(size_t)DFF * EE],  g_w1l[(size_t)DFF * EE];
__device__ __half g_w2h[(size_t)EE * DFF],  g_w2l[(size_t)EE * DFF];

// ---------------------------------------------------------------------------
// helpers
// ---------------------------------------------------------------------------
__device__ __forceinline__ uint32_t smem_u32(const void* p) {
    uint32_t a;
    asm("{ .reg .u64 t; cvta.to.shared.u64 t, %1; cvt.u32.u64 %0, t; }"
        : "=r"(a) : "l"(p));
    return a;
}
__device__ __forceinline__ void cpasync16(uint32_t s, const void* g) {
    asm volatile("cp.async.cg.shared.global [%0], [%1], 16;" :: "r"(s), "l"(g));
}
__device__ __forceinline__ void ldsm4(uint32_t r[4], uint32_t addr) {
    asm volatile("ldmatrix.sync.aligned.m8n8.x4.shared.b16 {%0,%1,%2,%3}, [%4];"
                 : "=r"(r[0]), "=r"(r[1]), "=r"(r[2]), "=r"(r[3]) : "r"(addr));
}
__device__ __forceinline__ void mma16816(float c[4], const uint32_t a[4],
                                         uint32_t b0, uint32_t b1) {
    asm volatile(
        "mma.sync.aligned.m16n8k16.row.col.f32.f16.f16.f32 "
        "{%0,%1,%2,%3}, {%4,%5,%6,%7}, {%8,%9}, {%0,%1,%2,%3};"
        : "+f"(c[0]), "+f"(c[1]), "+f"(c[2]), "+f"(c[3])
        : "r"(a[0]), "r"(a[1]), "r"(a[2]), "r"(a[3]), "r"(b0), "r"(b1));
}
__device__ __forceinline__ uint32_t packh2(float x, float y) {
    __half2 h = __floats2half2_rn(x, y);
    return *reinterpret_cast<uint32_t*>(&h);
}

// ---------------------------------------------------------------------------
// one-time conversions
// ---------------------------------------------------------------------------
// fp32 -> fp16 hi/lo split (weights)
__global__ __launch_bounds__(256)
void splitw_kernel(const float* __restrict__ in, __half* __restrict__ hi,
                   __half* __restrict__ lo, int n4)
{
    int i = blockIdx.x * blockDim.x + threadIdx.x;
    if (i >= n4) return;
    float4 v = ((const float4*)in)[i];
    __half h0 = __float2half_rn(v.x);
    __half h1 = __float2half_rn(v.y);
    __half h2 = __float2half_rn(v.z);
    __half h3 = __float2half_rn(v.w);
    uint2 hp, lp;
    hp.x = packh2(__half2float(h0), 0.f) | (packh2(__half2float(h1), 0.f) << 16);
    // simpler: re-pack directly
    hp.x = (uint32_t)*(unsigned short*)&h0 | ((uint32_t)*(unsigned short*)&h1 << 16);
    hp.y = (uint32_t)*(unsigned short*)&h2 | ((uint32_t)*(unsigned short*)&h3 << 16);
    lp.x = packh2(v.x - __half2float(h0), v.y - __half2float(h1));
    lp.y = packh2(v.z - __half2float(h2), v.w - __half2float(h3));
    ((uint2*)hi)[i] = hp;
    ((uint2*)lo)[i] = lp;
}
// fp32 -> fp16 (activations)
__global__ __launch_bounds__(256)
void cvt_kernel(const float* __restrict__ in, __half* __restrict__ o, int n4)
{
    int i = blockIdx.x * blockDim.x + threadIdx.x;
    if (i >= n4) return;
    float4 v = ((const float4*)in)[i];
    uint2 p;
    p.x = packh2(v.x, v.y);
    p.y = packh2(v.z, v.w);
    ((uint2*)o)[i] = p;
}

// ---------------------------------------------------------------------------
// Tensor-core GEMM, fp16 2-pass (A rounded, B split hi/lo):
//   C = A[M,K] @ B[N,K]^T + bias = A*Bh + A*Bl + bias
// CTA 128x128, BK=32, 256 threads (8 warps, warp tile 32x64).
// cp.async 2-stage pipeline; smem rows 64B data + 16B pad (80B stride).
// EPI: 0 = bias -> fp32 C;  1 = bias+relu -> fp16 plane C16.
// ---------------------------------------------------------------------------
#define TSTRIDE 80
#define PLANE   (128 * TSTRIDE)          // 10240 B
#define STAGE   (3 * PLANE)              // A, Bh, Bl = 30720 B
#define GSMEM   (2 * STAGE)              // 61440 B

template <int EPI>
__global__ __launch_bounds__(256, 2)
void gemm_mma(const __half* __restrict__ Ag,
              const __half* __restrict__ Bgh, const __half* __restrict__ Bgl,
              const float* __restrict__ bias,
              float* __restrict__ C, __half* __restrict__ C16,
              int Ndim, int Kdim)
{
    extern __shared__ char sm[];
    const int t    = threadIdx.x;
    const int lane = t & 31;
    const int wid  = t >> 5;
    const int wm   = (wid & 3) * 32;
    const int wn   = (wid >> 2) * 64;
    const int bm   = blockIdx.y * 128;
    const int bn   = blockIdx.x * 128;

    const uint32_t smb = smem_u32(sm);

    auto issue = [&](int k0, int buf) {
        uint32_t sb = smb + buf * STAGE;
#pragma unroll
        for (int i = 0; i < 2; i++) {
            int e = t + i * 256;                  // 0..511
            int r = e >> 2, c = e & 3;            // r 0..127, c 0..3 (16B units)
            uint32_t off = (uint32_t)(r * TSTRIDE + c * 16);
            size_t ga = (size_t)(bm + r) * Kdim + k0 + c * 8;
            size_t gb = (size_t)(bn + r) * Kdim + k0 + c * 8;
            cpasync16(sb + off,             Ag  + ga);
            cpasync16(sb + PLANE + off,     Bgh + gb);
            cpasync16(sb + 2 * PLANE + off, Bgl + gb);
        }
        asm volatile("cp.async.commit_group;");
    };

    float acc[2][8][4];
#pragma unroll
    for (int i = 0; i < 2; i++)
#pragma unroll
        for (int j = 0; j < 8; j++)
#pragma unroll
            for (int k = 0; k < 4; k++) acc[i][j][k] = 0.0f;

    const int kc = Kdim / 32;
    issue(0, 0);

    for (int ic = 0; ic < kc; ic++) {
        const int buf = ic & 1;
        if (ic + 1 < kc) {
            issue((ic + 1) * 32, buf ^ 1);
            asm volatile("cp.async.wait_group 1;");
        } else {
            asm volatile("cp.async.wait_group 0;");
        }
        __syncthreads();

        const uint32_t pA  = smb + buf * STAGE;
        const uint32_t pBh = pA + PLANE;
        const uint32_t pBl = pA + 2 * PLANE;

#pragma unroll
        for (int ks = 0; ks < 2; ks++) {
            uint32_t Af[2][4];
#pragma unroll
            for (int i = 0; i < 2; i++) {
                uint32_t off = (uint32_t)((wm + i * 16 + (lane & 15)) * TSTRIDE
                               + ks * 32 + ((lane >> 4) << 4));
                ldsm4(Af[i], pA + off);
            }
#pragma unroll
            for (int bh2 = 0; bh2 < 2; bh2++) {
                uint32_t Bf[2][4];
                uint32_t boff[2];
#pragma unroll
                for (int g = 0; g < 2; g++) {
                    int nb = wn + bh2 * 32 + g * 16;
                    uint32_t off = (uint32_t)((nb + (lane & 7) + ((lane >> 4) << 3)) * TSTRIDE
                                   + ks * 32 + (((lane >> 3) & 1) << 4));
                    boff[g] = off;
                    ldsm4(Bf[g], pBh + off);
                }
                // pass 1: A * Bh
#pragma unroll
                for (int g = 0; g < 2; g++)
#pragma unroll
                    for (int jj = 0; jj < 2; jj++) {
                        int j = bh2 * 4 + g * 2 + jj;
#pragma unroll
                        for (int i = 0; i < 2; i++)
                            mma16816(acc[i][j], Af[i], Bf[g][jj * 2], Bf[g][jj * 2 + 1]);
                    }
                // pass 2: A * Bl
#pragma unroll
                for (int g = 0; g < 2; g++) ldsm4(Bf[g], pBl + boff[g]);
#pragma unroll
                for (int g = 0; g < 2; g++)
#pragma unroll
                    for (int jj = 0; jj < 2; jj++) {
                        int j = bh2 * 4 + g * 2 + jj;
#pragma unroll
                        for (int i = 0; i < 2; i++)
                            mma16816(acc[i][j], Af[i], Bf[g][jj * 2], Bf[g][jj * 2 + 1]);
                    }
            }
        }
        __syncthreads();
    }

    // epilogue
#pragma unroll
    for (int i = 0; i < 2; i++) {
        const int r0 = bm + wm + i * 16 + (lane >> 2);
#pragma unroll
        for (int j = 0; j < 8; j++) {
            const int c = bn + wn + j * 8 + 2 * (lane & 3);
            const float bx = bias[c], by = bias[c + 1];
            float v0x = acc[i][j][0] + bx, v0y = acc[i][j][1] + by;
            float v1x = acc[i][j][2] + bx, v1y = acc[i][j][3] + by;
            if (EPI == 0) {
                *(float2*)(C + (size_t)r0 * Ndim + c)       = make_float2(v0x, v0y);
                *(float2*)(C + (size_t)(r0 + 8) * Ndim + c) = make_float2(v1x, v1y);
            } else {
                v0x = fmaxf(v0x, 0.f); v0y = fmaxf(v0y, 0.f);
                v1x = fmaxf(v1x, 0.f); v1y = fmaxf(v1y, 0.f);
                *(uint32_t*)(C16 + (size_t)r0 * Ndim + c)       = packh2(v0x, v0y);
                *(uint32_t*)(C16 + (size_t)(r0 + 8) * Ndim + c) = packh2(v1x, v1y);
            }
        }
    }
}

// ---------------------------------------------------------------------------
// Flash attention, fp32 SIMT; output written as fp16 plane
// ---------------------------------------------------------------------------
__global__ __launch_bounds__(256)
void attn_kernel(const float* __restrict__ qkv, __half* __restrict__ ctx16)
{
    __shared__ float Qs[64][64];
    __shared__ float Ks[32][65];
    __shared__ float Vs[32][64];
    __shared__ float Ps[64][33];

    const int qt = blockIdx.x & 15;
    const int bh = blockIdx.x >> 4;
    const int b  = bh / HH;
    const int h  = bh % HH;

    const int t = threadIdx.x;
    const int r = t >> 2;
    const int q = t & 3;

    const size_t rowstride = (size_t)BB * E3;
    const float* Qg = qkv + ((size_t)(qt * 64) * BB + b) * E3 + h * DD;
    const float* Kg = qkv + (size_t)b * E3 + EE + h * DD;
    const float* Vg = Kg + EE;

#pragma unroll
    for (int i = 0; i < 16; i++) {
        int e = t + i * 256;
        int row = e >> 6, col = e & 63;
        Qs[row][col] = Qg[(size_t)row * rowstride + col] * 0.125f;
    }

    float o[16];
#pragma unroll
    for (int dd = 0; dd < 16; dd++) o[dd] = 0.0f;
    float m_i = -1e30f, l_i = 0.0f;

    __syncthreads();

    for (int kt = 0; kt < SQ / 32; kt++) {
#pragma unroll
        for (int i = 0; i < 8; i++) {
            int e = t + i * 256;
            int row = e >> 6, col = e & 63;
            size_t goff = (size_t)(kt * 32 + row) * rowstride + col;
            Ks[row][col] = Kg[goff];
            Vs[row][col] = Vg[goff];
        }
        __syncthreads();

        float sacc[8] = {0, 0, 0, 0, 0, 0, 0, 0};
        const int kb = q * 8;
#pragma unroll 8
        for (int d = 0; d < 64; d++) {
            float qd = Qs[r][d];
#pragma unroll
            for (int j = 0; j < 8; j++)
                sacc[j] = fmaf(qd, Ks[kb + j][d], sacc[j]);
        }

        float tmax = sacc[0];
#pragma unroll
        for (int j = 1; j < 8; j++) tmax = fmaxf(tmax, sacc[j]);
        tmax = fmaxf(tmax, __shfl_xor_sync(0xffffffffu, tmax, 1));
        tmax = fmaxf(tmax, __shfl_xor_sync(0xffffffffu, tmax, 2));

        float new_m = fmaxf(m_i, tmax);
        float corr  = __expf(m_i - new_m);

        float tsum = 0.0f;
        float p[8];
#pragma unroll
        for (int j = 0; j < 8; j++) {
            p[j] = __expf(sacc[j] - new_m);
            tsum += p[j];
        }
        tsum += __shfl_xor_sync(0xffffffffu, tsum, 1);
        tsum += __shfl_xor_sync(0xffffffffu, tsum, 2);

        l_i = l_i * corr + tsum;
        m_i = new_m;
#pragma unroll
        for (int dd = 0; dd < 16; dd++) o[dd] *= corr;
#pragma unroll
        for (int j = 0; j < 8; j++) Ps[r][kb + j] = p[j];
        __syncthreads();

#pragma unroll 4
        for (int k = 0; k < 32; k++) {
            float pv = Ps[r][k];
#pragma unroll
            for (int dd = 0; dd < 16; dd++)
                o[dd] = fmaf(pv, Vs[k][q + dd * 4], o[dd]);
        }
        __syncthreads();
    }

    float inv_l = 1.0f / l_i;
    const int srow = qt * 64 + r;
    const size_t obase = ((size_t)srow * BB + b) * EE + h * DD;
#pragma unroll
    for (int dd = 0; dd < 16; dd++)
        ctx16[obase + q + dd * 4] = __float2half_rn(o[dd] * inv_l);
}

// ---------------------------------------------------------------------------
// out = layernorm(a + b) * g + beta; CVT=1 also writes fp16 plane
// ---------------------------------------------------------------------------
template <int CVT>
__global__ __launch_bounds__(256)
void add_ln_kernel(const float* __restrict__ a, const float* __restrict__ bres,
                   const float* __restrict__ g, const float* __restrict__ beta,
                   float* __restrict__ out, __half* __restrict__ o16)
{
    const int row = blockIdx.x;
    const int t   = threadIdx.x;
    const float4* A4 = (const float4*)(a    + (size_t)row * EE);
    const float4* B4 = (const float4*)(bres + (size_t)row * EE);

    float4 x = A4[t];
    float4 y = B4[t];
    x.x += y.x; x.y += y.y; x.z += y.z; x.w += y.w;

    float s  = x.x + x.y + x.z + x.w;
    float ss = x.x * x.x + x.y * x.y + x.z * x.z + x.w * x.w;

#pragma unroll
    for (int off = 16; off > 0; off >>= 1) {
        s  += __shfl_xor_sync(0xffffffffu, s,  off);
        ss += __shfl_xor_sync(0xffffffffu, ss, off);
    }
    __shared__ float sh_s[8], sh_ss[8];
    const int w = t >> 5, l = t & 31;
    if (l == 0) { sh_s[w] = s; sh_ss[w] = ss; }
    __syncthreads();
    s = 0.0f; ss = 0.0f;
#pragma unroll
    for (int i = 0; i < 8; i++) { s += sh_s[i]; ss += sh_ss[i]; }

    const float mean = s * (1.0f / EE);
    const float var  = ss * (1.0f / EE) - mean * mean;
    const float rstd = rsqrtf(var + 1e-5f);

    float4 g4 = ((const float4*)g)[t];
    float4 b4 = ((const float4*)beta)[t];
    float4 o;
    o.x = (x.x - mean) * rstd * g4.x + b4.x;
    o.y = (x.y - mean) * rstd * g4.y + b4.y;
    o.z = (x.z - mean) * rstd * g4.z + b4.z;
    o.w = (x.w - mean) * rstd * g4.w + b4.w;
    ((float4*)(out + (size_t)row * EE))[t] = o;

    if (CVT) {
        uint2 p;
        p.x = packh2(o.x, o.y);
        p.y = packh2(o.z, o.w);
        ((uint2*)(o16 + (size_t)row * EE))[t] = p;
    }
}

// ---------------------------------------------------------------------------
// launch
// ---------------------------------------------------------------------------
extern "C" void kernel_launch(void* const* d_in, const int* in_sizes, int n_in,
                              void* d_out, int out_size)
{
    const float* src    = (const float*)d_in[0];
    const float* in_w   = (const float*)d_in[1];
    const float* in_b   = (const float*)d_in[2];
    const float* out_w  = (const float*)d_in[3];
    const float* out_b  = (const float*)d_in[4];
    const float* ln1g   = (const float*)d_in[5];
    const float* ln1b   = (const float*)d_in[6];
    const float* ln2g   = (const float*)d_in[7];
    const float* ln2b   = (const float*)d_in[8];
    const float* w1     = (const float*)d_in[9];
    const float* b1     = (const float*)d_in[10];
    const float* w2     = (const float*)d_in[11];
    const float* b2     = (const float*)d_in[12];
    float* out = (float*)d_out;

    float *qkv, *tmp, *x;
    cudaGetSymbolAddress((void**)&qkv, g_qkv);
    cudaGetSymbolAddress((void**)&tmp, g_tmp);
    cudaGetSymbolAddress((void**)&x,   g_x);

    __half *src16, *ctx16, *x16, *ff116;
    __half *inwh, *inwl, *outwh, *outwl, *w1h, *w1l, *w2h, *w2l;
    cudaGetSymbolAddress((void**)&src16, g_src16);
    cudaGetSymbolAddress((void**)&ctx16, g_ctx16);
    cudaGetSymbolAddress((void**)&x16,   g_x16);
    cudaGetSymbolAddress((void**)&ff116, g_ff116);
    cudaGetSymbolAddress((void**)&inwh, g_inwh);   cudaGetSymbolAddress((void**)&inwl, g_inwl);
    cudaGetSymbolAddress((void**)&outwh, g_outwh); cudaGetSymbolAddress((void**)&outwl, g_outwl);
    cudaGetSymbolAddress((void**)&w1h,  g_w1h);    cudaGetSymbolAddress((void**)&w1l,  g_w1l);
    cudaGetSymbolAddress((void**)&w2h,  g_w2h);    cudaGetSymbolAddress((void**)&w2l,  g_w2l);

    cudaFuncSetAttribute(gemm_mma<0>, cudaFuncAttributeMaxDynamicSharedMemorySize, GSMEM);
    cudaFuncSetAttribute(gemm_mma<1>, cudaFuncAttributeMaxDynamicSharedMemorySize, GSMEM);

    // 0. one-time conversions
    auto splitw = [&](const float* p, __half* h, __half* l, size_t n) {
        int n4 = (int)(n / 4);
        splitw_kernel<<<(n4 + 255) / 256, 256>>>(p, h, l, n4);
    };
    splitw(in_w,  inwh,  inwl,  (size_t)E3 * EE);
    splitw(out_w, outwh, outwl, (size_t)EE * EE);
    splitw(w1,    w1h,   w1l,   (size_t)DFF * EE);
    splitw(w2,    w2h,   w2l,   (size_t)EE * DFF);
    {
        int n4 = (int)((size_t)MTOK * EE / 4);
        cvt_kernel<<<(n4 + 255) / 256, 256>>>(src, src16, n4);
    }

    // 1. qkv = src @ in_proj_w^T + b        (8192 x 3072 x 1024) -> fp32
    gemm_mma<0><<<dim3(E3 / 128, MTOK / 128), 256, GSMEM>>>(
        src16, inwh, inwl, in_b, qkv, nullptr, E3, EE);
    // 2. flash attention -> ctx fp16
    attn_kernel<<<BB * HH * (SQ / 64), 256>>>(qkv, ctx16);
    // 3. attn_out = ctx @ out_w^T + out_b   (8192 x 1024 x 1024) -> fp32 tmp
    gemm_mma<0><<<dim3(EE / 128, MTOK / 128), 256, GSMEM>>>(
        ctx16, outwh, outwl, out_b, tmp, nullptr, EE, EE);
    // 4. x = LN1(src + attn_out) -> fp32 x + fp16 x16
    add_ln_kernel<1><<<MTOK, 256>>>(src, tmp, ln1g, ln1b, x, x16);
    // 5. ff1 = relu(x @ w1^T + b1)          (8192 x 4096 x 1024) -> fp16
    gemm_mma<1><<<dim3(DFF / 128, MTOK / 128), 256, GSMEM>>>(
        x16, w1h, w1l, b1, nullptr, ff116, DFF, EE);
    // 6. ff2 = ff1 @ w2^T + b2              (8192 x 1024 x 4096) -> fp32 tmp
    gemm_mma<0><<<dim3(EE / 128, MTOK / 128), 256, GSMEM>>>(
        ff116, w2h, w2l, b2, tmp, nullptr, EE, DFF);
    // 7. out = LN2(x + ff2)
    add_ln_kernel<0><<<MTOK, 256>>>(x, tmp, ln2g, ln2b, out, nullptr);
}

// round 10
// speedup vs baseline: 5.2801x; 2.4897x over previous
#include <cuda_runtime.h>
#include <cuda_fp16.h>
#include <cstdint>
#include <cstddef>

// Problem constants
#define SQ   1024
#define BB   8
#define EE   1024
#define HH   16
#define DD   64
#define DFF  4096
#define MTOK (SQ * BB)     // 8192
#define E3   (3 * EE)      // 3072

// ---------------------------------------------------------------------------
// Scratch (__device__ globals; no allocations allowed)
// ---------------------------------------------------------------------------
__device__ float g_tmp[(size_t)MTOK * EE];
__device__ float g_x  [(size_t)MTOK * EE];

// fp16 single-plane activations
__device__ __half g_qkv16[(size_t)MTOK * E3];
__device__ __half g_src16[(size_t)MTOK * EE];
__device__ __half g_ctx16[(size_t)MTOK * EE];
__device__ __half g_x16  [(size_t)MTOK * EE];
__device__ __half g_ff116[(size_t)MTOK * DFF];

// fp16 hi/lo weight planes
__device__ __half g_inwh[(size_t)E3 * EE],  g_inwl[(size_t)E3 * EE];
__device__ __half g_outwh[(size_t)EE * EE], g_outwl[(size_t)EE * EE];
__device__ __half g_w1h[(size_t)DFF * EE],  g_w1l[(size_t)DFF * EE];
__device__ __half g_w2h[(size_t)EE * DFF],  g_w2l[(size_t)EE * DFF];

// ---------------------------------------------------------------------------
// helpers
// ---------------------------------------------------------------------------
__device__ __forceinline__ uint32_t smem_u32(const void* p) {
    uint32_t a;
    asm("{ .reg .u64 t; cvta.to.shared.u64 t, %1; cvt.u32.u64 %0, t; }"
        : "=r"(a) : "l"(p));
    return a;
}
__device__ __forceinline__ void cpasync16(uint32_t s, const void* g) {
    asm volatile("cp.async.cg.shared.global [%0], [%1], 16;" :: "r"(s), "l"(g));
}
__device__ __forceinline__ void ldsm4(uint32_t r[4], uint32_t addr) {
    asm volatile("ldmatrix.sync.aligned.m8n8.x4.shared.b16 {%0,%1,%2,%3}, [%4];"
                 : "=r"(r[0]), "=r"(r[1]), "=r"(r[2]), "=r"(r[3]) : "r"(addr));
}
__device__ __forceinline__ void ldsm4t(uint32_t r[4], uint32_t addr) {
    asm volatile("ldmatrix.sync.aligned.m8n8.x4.trans.shared.b16 {%0,%1,%2,%3}, [%4];"
                 : "=r"(r[0]), "=r"(r[1]), "=r"(r[2]), "=r"(r[3]) : "r"(addr));
}
__device__ __forceinline__ void mma16816(float c[4], const uint32_t a[4],
                                         uint32_t b0, uint32_t b1) {
    asm volatile(
        "mma.sync.aligned.m16n8k16.row.col.f32.f16.f16.f32 "
        "{%0,%1,%2,%3}, {%4,%5,%6,%7}, {%8,%9}, {%0,%1,%2,%3};"
        : "+f"(c[0]), "+f"(c[1]), "+f"(c[2]), "+f"(c[3])
        : "r"(a[0]), "r"(a[1]), "r"(a[2]), "r"(a[3]), "r"(b0), "r"(b1));
}
__device__ __forceinline__ uint32_t packh2(float x, float y) {
    __half2 h = __floats2half2_rn(x, y);
    return *reinterpret_cast<uint32_t*>(&h);
}

// ---------------------------------------------------------------------------
// one-time conversions
// ---------------------------------------------------------------------------
__global__ __launch_bounds__(256)
void splitw_kernel(const float* __restrict__ in, __half* __restrict__ hi,
                   __half* __restrict__ lo, int n4)
{
    int i = blockIdx.x * blockDim.x + threadIdx.x;
    if (i >= n4) return;
    float4 v = ((const float4*)in)[i];
    __half h0 = __float2half_rn(v.x);
    __half h1 = __float2half_rn(v.y);
    __half h2 = __float2half_rn(v.z);
    __half h3 = __float2half_rn(v.w);
    uint2 hp, lp;
    hp.x = (uint32_t)*(unsigned short*)&h0 | ((uint32_t)*(unsigned short*)&h1 << 16);
    hp.y = (uint32_t)*(unsigned short*)&h2 | ((uint32_t)*(unsigned short*)&h3 << 16);
    lp.x = packh2(v.x - __half2float(h0), v.y - __half2float(h1));
    lp.y = packh2(v.z - __half2float(h2), v.w - __half2float(h3));
    ((uint2*)hi)[i] = hp;
    ((uint2*)lo)[i] = lp;
}
__global__ __launch_bounds__(256)
void cvt_kernel(const float* __restrict__ in, __half* __restrict__ o, int n4)
{
    int i = blockIdx.x * blockDim.x + threadIdx.x;
    if (i >= n4) return;
    float4 v = ((const float4*)in)[i];
    uint2 p;
    p.x = packh2(v.x, v.y);
    p.y = packh2(v.z, v.w);
    ((uint2*)o)[i] = p;
}

// ---------------------------------------------------------------------------
// Tensor-core GEMM, fp16 2-pass (A rounded, B split hi/lo):
//   C = A[M,K] @ B[N,K]^T + bias = A*Bh + A*Bl + bias
// EPI: 0 = bias -> fp32 C;  1 = bias+relu -> fp16 C16;  2 = bias -> fp16 C16
// ---------------------------------------------------------------------------
#define TSTRIDE 80
#define PLANE   (128 * TSTRIDE)
#define STAGE   (3 * PLANE)
#define GSMEM   (2 * STAGE)

template <int EPI>
__global__ __launch_bounds__(256, 2)
void gemm_mma(const __half* __restrict__ Ag,
              const __half* __restrict__ Bgh, const __half* __restrict__ Bgl,
              const float* __restrict__ bias,
              float* __restrict__ C, __half* __restrict__ C16,
              int Ndim, int Kdim)
{
    extern __shared__ char sm[];
    const int t    = threadIdx.x;
    const int lane = t & 31;
    const int wid  = t >> 5;
    const int wm   = (wid & 3) * 32;
    const int wn   = (wid >> 2) * 64;
    const int bm   = blockIdx.y * 128;
    const int bn   = blockIdx.x * 128;

    const uint32_t smb = smem_u32(sm);

    auto issue = [&](int k0, int buf) {
        uint32_t sb = smb + buf * STAGE;
#pragma unroll
        for (int i = 0; i < 2; i++) {
            int e = t + i * 256;
            int r = e >> 2, c = e & 3;
            uint32_t off = (uint32_t)(r * TSTRIDE + c * 16);
            size_t ga = (size_t)(bm + r) * Kdim + k0 + c * 8;
            size_t gb = (size_t)(bn + r) * Kdim + k0 + c * 8;
            cpasync16(sb + off,             Ag  + ga);
            cpasync16(sb + PLANE + off,     Bgh + gb);
            cpasync16(sb + 2 * PLANE + off, Bgl + gb);
        }
        asm volatile("cp.async.commit_group;");
    };

    float acc[2][8][4];
#pragma unroll
    for (int i = 0; i < 2; i++)
#pragma unroll
        for (int j = 0; j < 8; j++)
#pragma unroll
            for (int k = 0; k < 4; k++) acc[i][j][k] = 0.0f;

    const int kc = Kdim / 32;
    issue(0, 0);

    for (int ic = 0; ic < kc; ic++) {
        const int buf = ic & 1;
        if (ic + 1 < kc) {
            issue((ic + 1) * 32, buf ^ 1);
            asm volatile("cp.async.wait_group 1;");
        } else {
            asm volatile("cp.async.wait_group 0;");
        }
        __syncthreads();

        const uint32_t pA  = smb + buf * STAGE;
        const uint32_t pBh = pA + PLANE;
        const uint32_t pBl = pA + 2 * PLANE;

#pragma unroll
        for (int ks = 0; ks < 2; ks++) {
            uint32_t Af[2][4];
#pragma unroll
            for (int i = 0; i < 2; i++) {
                uint32_t off = (uint32_t)((wm + i * 16 + (lane & 15)) * TSTRIDE
                               + ks * 32 + ((lane >> 4) << 4));
                ldsm4(Af[i], pA + off);
            }
#pragma unroll
            for (int bh2 = 0; bh2 < 2; bh2++) {
                uint32_t Bf[2][4];
                uint32_t boff[2];
#pragma unroll
                for (int g = 0; g < 2; g++) {
                    int nb = wn + bh2 * 32 + g * 16;
                    uint32_t off = (uint32_t)((nb + (lane & 7) + ((lane >> 4) << 3)) * TSTRIDE
                                   + ks * 32 + (((lane >> 3) & 1) << 4));
                    boff[g] = off;
                    ldsm4(Bf[g], pBh + off);
                }
#pragma unroll
                for (int g = 0; g < 2; g++)
#pragma unroll
                    for (int jj = 0; jj < 2; jj++) {
                        int j = bh2 * 4 + g * 2 + jj;
#pragma unroll
                        for (int i = 0; i < 2; i++)
                            mma16816(acc[i][j], Af[i], Bf[g][jj * 2], Bf[g][jj * 2 + 1]);
                    }
#pragma unroll
                for (int g = 0; g < 2; g++) ldsm4(Bf[g], pBl + boff[g]);
#pragma unroll
                for (int g = 0; g < 2; g++)
#pragma unroll
                    for (int jj = 0; jj < 2; jj++) {
                        int j = bh2 * 4 + g * 2 + jj;
#pragma unroll
                        for (int i = 0; i < 2; i++)
                            mma16816(acc[i][j], Af[i], Bf[g][jj * 2], Bf[g][jj * 2 + 1]);
                    }
            }
        }
        __syncthreads();
    }

#pragma unroll
    for (int i = 0; i < 2; i++) {
        const int r0 = bm + wm + i * 16 + (lane >> 2);
#pragma unroll
        for (int j = 0; j < 8; j++) {
            const int c = bn + wn + j * 8 + 2 * (lane & 3);
            const float bx = bias[c], by = bias[c + 1];
            float v0x = acc[i][j][0] + bx, v0y = acc[i][j][1] + by;
            float v1x = acc[i][j][2] + bx, v1y = acc[i][j][3] + by;
            if (EPI == 0) {
                *(float2*)(C + (size_t)r0 * Ndim + c)       = make_float2(v0x, v0y);
                *(float2*)(C + (size_t)(r0 + 8) * Ndim + c) = make_float2(v1x, v1y);
            } else {
                if (EPI == 1) {
                    v0x = fmaxf(v0x, 0.f); v0y = fmaxf(v0y, 0.f);
                    v1x = fmaxf(v1x, 0.f); v1y = fmaxf(v1y, 0.f);
                }
                *(uint32_t*)(C16 + (size_t)r0 * Ndim + c)       = packh2(v0x, v0y);
                *(uint32_t*)(C16 + (size_t)(r0 + 8) * Ndim + c) = packh2(v1x, v1y);
            }
        }
    }
}

// ---------------------------------------------------------------------------
// Flash attention via mma.sync fp16.
// Block: 64 queries x one (b,h); 4 warps, 16 q-rows each; 16 key tiles of 64.
// S frags feed P·V directly (no smem round-trip for P).
// ---------------------------------------------------------------------------
#define ATS 144                      // smem row stride (128B data + 16B pad)
#define ATILE (64 * ATS)             // 9216 B

__global__ __launch_bounds__(128)
void attn_mma(const __half* __restrict__ qkv, __half* __restrict__ ctx)
{
    __shared__ __align__(16) char smQ[ATILE];
    __shared__ __align__(16) char smK[2][ATILE];
    __shared__ __align__(16) char smV[2][ATILE];

    const int qt = blockIdx.x & 15;
    const int bh = blockIdx.x >> 4;
    const int b  = bh / HH;
    const int h  = bh % HH;
    const int t  = threadIdx.x;
    const int lane = t & 31;
    const int w  = t >> 5;
    const int q0 = w * 16;

    const size_t rowstride = (size_t)BB * E3;
    const __half* Qg = qkv + ((size_t)(qt * 64) * BB + b) * E3 + h * DD;
    const __half* Kg = qkv + (size_t)b * E3 + EE + h * DD;
    const __half* Vg = Kg + EE;

    const uint32_t uQ = smem_u32(smQ);
    const uint32_t uK = smem_u32(smK[0]);
    const uint32_t uV = smem_u32(smV[0]);

    auto issue_kv = [&](int kt, int buf) {
#pragma unroll
        for (int i = 0; i < 4; i++) {
            int e = t + i * 128;
            int r = e >> 3, c = e & 7;
            uint32_t off = (uint32_t)(r * ATS + c * 16) + (uint32_t)(buf * ATILE);
            size_t g = (size_t)(kt * 64 + r) * rowstride + c * 8;
            cpasync16(uK + off, Kg + g);
            cpasync16(uV + off, Vg + g);
        }
        asm volatile("cp.async.commit_group;");
    };

    // group 0: Q + KV tile 0
#pragma unroll
    for (int i = 0; i < 4; i++) {
        int e = t + i * 128;
        int r = e >> 3, c = e & 7;
        uint32_t off = (uint32_t)(r * ATS + c * 16);
        size_t g = (size_t)r * rowstride + c * 8;
        cpasync16(uQ + off, Qg + g);
        cpasync16(uK + off, Kg + g);
        cpasync16(uV + off, Vg + g);
    }
    asm volatile("cp.async.commit_group;");

    uint32_t Aq[4][4];
    float oacc[8][4];
#pragma unroll
    for (int j = 0; j < 8; j++)
#pragma unroll
        for (int e = 0; e < 4; e++) oacc[j][e] = 0.0f;
    float m0 = -1e30f, m1 = -1e30f, l0 = 0.0f, l1 = 0.0f;

    for (int kt = 0; kt < 16; kt++) {
        const int buf = kt & 1;
        if (kt + 1 < 16) {
            issue_kv(kt + 1, buf ^ 1);
            asm volatile("cp.async.wait_group 1;");
        } else {
            asm volatile("cp.async.wait_group 0;");
        }
        __syncthreads();

        if (kt == 0) {
#pragma unroll
            for (int ks = 0; ks < 4; ks++) {
                uint32_t off = (uint32_t)((q0 + (lane & 15)) * ATS + ks * 32 + ((lane >> 4) << 4));
                ldsm4(Aq[ks], uQ + off);
            }
        }
        const uint32_t pK = uK + buf * ATILE;
        const uint32_t pV = uV + buf * ATILE;

        // S = Q @ K^T  (scaled later)
        float sacc[8][4];
#pragma unroll
        for (int j = 0; j < 8; j++)
#pragma unroll
            for (int e = 0; e < 4; e++) sacc[j][e] = 0.0f;
#pragma unroll
        for (int ks = 0; ks < 4; ks++) {
#pragma unroll
            for (int g = 0; g < 4; g++) {
                uint32_t Kf[4];
                uint32_t off = (uint32_t)((g * 16 + (lane & 7) + ((lane >> 4) << 3)) * ATS
                               + ks * 32 + (((lane >> 3) & 1) << 4));
                ldsm4(Kf, pK + off);
                mma16816(sacc[g * 2],     Aq[ks], Kf[0], Kf[1]);
                mma16816(sacc[g * 2 + 1], Aq[ks], Kf[2], Kf[3]);
            }
        }

        // online softmax (rows r=lane>>2 and r+8; cols on 4-lane groups)
        float mx0 = -1e30f, mx1 = -1e30f;
#pragma unroll
        for (int j = 0; j < 8; j++) {
            sacc[j][0] *= 0.125f; sacc[j][1] *= 0.125f;
            sacc[j][2] *= 0.125f; sacc[j][3] *= 0.125f;
            mx0 = fmaxf(mx0, fmaxf(sacc[j][0], sacc[j][1]));
            mx1 = fmaxf(mx1, fmaxf(sacc[j][2], sacc[j][3]));
        }
        mx0 = fmaxf(mx0, __shfl_xor_sync(0xffffffffu, mx0, 1));
        mx0 = fmaxf(mx0, __shfl_xor_sync(0xffffffffu, mx0, 2));
        mx1 = fmaxf(mx1, __shfl_xor_sync(0xffffffffu, mx1, 1));
        mx1 = fmaxf(mx1, __shfl_xor_sync(0xffffffffu, mx1, 2));

        float nm0 = fmaxf(m0, mx0), nm1 = fmaxf(m1, mx1);
        float c0 = __expf(m0 - nm0), c1 = __expf(m1 - nm1);

        float s0 = 0.0f, s1 = 0.0f;
        uint32_t Pa[4][4];
#pragma unroll
        for (int j = 0; j < 8; j++) {
            float p0 = __expf(sacc[j][0] - nm0);
            float p1 = __expf(sacc[j][1] - nm0);
            float p2 = __expf(sacc[j][2] - nm1);
            float p3 = __expf(sacc[j][3] - nm1);
            s0 += p0 + p1; s1 += p2 + p3;
            const int ks = j >> 1, hi = j & 1;
            Pa[ks][hi * 2]     = packh2(p0, p1);
            Pa[ks][hi * 2 + 1] = packh2(p2, p3);
        }
        s0 += __shfl_xor_sync(0xffffffffu, s0, 1);
        s0 += __shfl_xor_sync(0xffffffffu, s0, 2);
        s1 += __shfl_xor_sync(0xffffffffu, s1, 1);
        s1 += __shfl_xor_sync(0xffffffffu, s1, 2);

        l0 = l0 * c0 + s0;  l1 = l1 * c1 + s1;
        m0 = nm0;           m1 = nm1;
#pragma unroll
        for (int j = 0; j < 8; j++) {
            oacc[j][0] *= c0; oacc[j][1] *= c0;
            oacc[j][2] *= c1; oacc[j][3] *= c1;
        }

        // O += P @ V   (V via trans ldmatrix: row-major [key][d] -> B operand)
#pragma unroll
        for (int ks = 0; ks < 4; ks++) {
#pragma unroll
            for (int dg = 0; dg < 4; dg++) {
                uint32_t Vf[4];
                uint32_t off = (uint32_t)((ks * 16 + (lane & 7) + (((lane >> 3) & 1) << 3)) * ATS
                               + dg * 32 + ((lane >> 4) << 4));
                ldsm4t(Vf, pV + off);
                mma16816(oacc[dg * 2],     Pa[ks], Vf[0], Vf[1]);
                mma16816(oacc[dg * 2 + 1], Pa[ks], Vf[2], Vf[3]);
            }
        }
        __syncthreads();
    }

    const float i0 = 1.0f / l0, i1 = 1.0f / l1;
    const int r0 = qt * 64 + q0 + (lane >> 2);
#pragma unroll
    for (int j = 0; j < 8; j++) {
        const int col = h * DD + j * 8 + 2 * (lane & 3);
        *(uint32_t*)(ctx + ((size_t)r0 * BB + b) * EE + col) =
            packh2(oacc[j][0] * i0, oacc[j][1] * i0);
        *(uint32_t*)(ctx + ((size_t)(r0 + 8) * BB + b) * EE + col) =
            packh2(oacc[j][2] * i1, oacc[j][3] * i1);
    }
}

// ---------------------------------------------------------------------------
// out = layernorm(a + b) * g + beta; CVT=1 also writes fp16 plane
// ---------------------------------------------------------------------------
template <int CVT>
__global__ __launch_bounds__(256)
void add_ln_kernel(const float* __restrict__ a, const float* __restrict__ bres,
                   const float* __restrict__ g, const float* __restrict__ beta,
                   float* __restrict__ out, __half* __restrict__ o16)
{
    const int row = blockIdx.x;
    const int t   = threadIdx.x;
    const float4* A4 = (const float4*)(a    + (size_t)row * EE);
    const float4* B4 = (const float4*)(bres + (size_t)row * EE);

    float4 x = A4[t];
    float4 y = B4[t];
    x.x += y.x; x.y += y.y; x.z += y.z; x.w += y.w;

    float s  = x.x + x.y + x.z + x.w;
    float ss = x.x * x.x + x.y * x.y + x.z * x.z + x.w * x.w;

#pragma unroll
    for (int off = 16; off > 0; off >>= 1) {
        s  += __shfl_xor_sync(0xffffffffu, s,  off);
        ss += __shfl_xor_sync(0xffffffffu, ss, off);
    }
    __shared__ float sh_s[8], sh_ss[8];
    const int w = t >> 5, l = t & 31;
    if (l == 0) { sh_s[w] = s; sh_ss[w] = ss; }
    __syncthreads();
    s = 0.0f; ss = 0.0f;
#pragma unroll
    for (int i = 0; i < 8; i++) { s += sh_s[i]; ss += sh_ss[i]; }

    const float mean = s * (1.0f / EE);
    const float var  = ss * (1.0f / EE) - mean * mean;
    const float rstd = rsqrtf(var + 1e-5f);

    float4 g4 = ((const float4*)g)[t];
    float4 b4 = ((const float4*)beta)[t];
    float4 o;
    o.x = (x.x - mean) * rstd * g4.x + b4.x;
    o.y = (x.y - mean) * rstd * g4.y + b4.y;
    o.z = (x.z - mean) * rstd * g4.z + b4.z;
    o.w = (x.w - mean) * rstd * g4.w + b4.w;
    ((float4*)(out + (size_t)row * EE))[t] = o;

    if (CVT) {
        uint2 p;
        p.x = packh2(o.x, o.y);
        p.y = packh2(o.z, o.w);
        ((uint2*)(o16 + (size_t)row * EE))[t] = p;
    }
}

// ---------------------------------------------------------------------------
// launch
// ---------------------------------------------------------------------------
extern "C" void kernel_launch(void* const* d_in, const int* in_sizes, int n_in,
                              void* d_out, int out_size)
{
    const float* src    = (const float*)d_in[0];
    const float* in_w   = (const float*)d_in[1];
    const float* in_b   = (const float*)d_in[2];
    const float* out_w  = (const float*)d_in[3];
    const float* out_b  = (const float*)d_in[4];
    const float* ln1g   = (const float*)d_in[5];
    const float* ln1b   = (const float*)d_in[6];
    const float* ln2g   = (const float*)d_in[7];
    const float* ln2b   = (const float*)d_in[8];
    const float* w1     = (const float*)d_in[9];
    const float* b1     = (const float*)d_in[10];
    const float* w2     = (const float*)d_in[11];
    const float* b2     = (const float*)d_in[12];
    float* out = (float*)d_out;

    float *tmp, *x;
    cudaGetSymbolAddress((void**)&tmp, g_tmp);
    cudaGetSymbolAddress((void**)&x,   g_x);

    __half *qkv16, *src16, *ctx16, *x16, *ff116;
    __half *inwh, *inwl, *outwh, *outwl, *w1h, *w1l, *w2h, *w2l;
    cudaGetSymbolAddress((void**)&qkv16, g_qkv16);
    cudaGetSymbolAddress((void**)&src16, g_src16);
    cudaGetSymbolAddress((void**)&ctx16, g_ctx16);
    cudaGetSymbolAddress((void**)&x16,   g_x16);
    cudaGetSymbolAddress((void**)&ff116, g_ff116);
    cudaGetSymbolAddress((void**)&inwh, g_inwh);   cudaGetSymbolAddress((void**)&inwl, g_inwl);
    cudaGetSymbolAddress((void**)&outwh, g_outwh); cudaGetSymbolAddress((void**)&outwl, g_outwl);
    cudaGetSymbolAddress((void**)&w1h,  g_w1h);    cudaGetSymbolAddress((void**)&w1l,  g_w1l);
    cudaGetSymbolAddress((void**)&w2h,  g_w2h);    cudaGetSymbolAddress((void**)&w2l,  g_w2l);

    cudaFuncSetAttribute(gemm_mma<0>, cudaFuncAttributeMaxDynamicSharedMemorySize, GSMEM);
    cudaFuncSetAttribute(gemm_mma<1>, cudaFuncAttributeMaxDynamicSharedMemorySize, GSMEM);
    cudaFuncSetAttribute(gemm_mma<2>, cudaFuncAttributeMaxDynamicSharedMemorySize, GSMEM);

    // 0. one-time conversions
    auto splitw = [&](const float* p, __half* h, __half* l, size_t n) {
        int n4 = (int)(n / 4);
        splitw_kernel<<<(n4 + 255) / 256, 256>>>(p, h, l, n4);
    };
    splitw(in_w,  inwh,  inwl,  (size_t)E3 * EE);
    splitw(out_w, outwh, outwl, (size_t)EE * EE);
    splitw(w1,    w1h,   w1l,   (size_t)DFF * EE);
    splitw(w2,    w2h,   w2l,   (size_t)EE * DFF);
    {
        int n4 = (int)((size_t)MTOK * EE / 4);
        cvt_kernel<<<(n4 + 255) / 256, 256>>>(src, src16, n4);
    }

    // 1. qkv = src @ in_proj_w^T + b        (8192 x 3072 x 1024) -> fp16
    gemm_mma<2><<<dim3(E3 / 128, MTOK / 128), 256, GSMEM>>>(
        src16, inwh, inwl, in_b, nullptr, qkv16, E3, EE);
    // 2. flash attention (mma.sync fp16) -> ctx fp16
    attn_mma<<<BB * HH * 16, 128>>>(qkv16, ctx16);
    // 3. attn_out = ctx @ out_w^T + out_b   (8192 x 1024 x 1024) -> fp32 tmp
    gemm_mma<0><<<dim3(EE / 128, MTOK / 128), 256, GSMEM>>>(
        ctx16, outwh, outwl, out_b, tmp, nullptr, EE, EE);
    // 4. x = LN1(src + attn_out) -> fp32 x + fp16 x16
    add_ln_kernel<1><<<MTOK, 256>>>(src, tmp, ln1g, ln1b, x, x16);
    // 5. ff1 = relu(x @ w1^T + b1)          (8192 x 4096 x 1024) -> fp16
    gemm_mma<1><<<dim3(DFF / 128, MTOK / 128), 256, GSMEM>>>(
        x16, w1h, w1l, b1, nullptr, ff116, DFF, EE);
    // 6. ff2 = ff1 @ w2^T + b2              (8192 x 1024 x 4096) -> fp32 tmp
    gemm_mma<0><<<dim3(EE / 128, MTOK / 128), 256, GSMEM>>>(
        ff116, w2h, w2l, b2, tmp, nullptr, EE, DFF);
    // 7. out = LN2(x + ff2)
    add_ln_kernel<0><<<MTOK, 256>>>(x, tmp, ln2g, ln2b, out, nullptr);
}

// round 12
// speedup vs baseline: 8.3349x; 1.5786x over previous
#include <cuda_runtime.h>
#include <cuda_fp16.h>
#include <cstdint>
#include <cstddef>

// Problem constants
#define SQ   1024
#define BB   8
#define EE   1024
#define HH   16
#define DD   64
#define DFF  4096
#define MTOK (SQ * BB)     // 8192
#define E3   (3 * EE)      // 3072

// ---------------------------------------------------------------------------
// Scratch (__device__ globals; no allocations allowed)
// ---------------------------------------------------------------------------
__device__ float g_tmp[(size_t)MTOK * EE];
__device__ float g_x  [(size_t)MTOK * EE];

// fp16 single-plane activations
__device__ __half g_qkv16[(size_t)MTOK * E3];
__device__ __half g_src16[(size_t)MTOK * EE];
__device__ __half g_ctx16[(size_t)MTOK * EE];
__device__ __half g_x16  [(size_t)MTOK * EE];
__device__ __half g_ff116[(size_t)MTOK * DFF];

// fp16 weights (single plane)
__device__ __half g_inw16[(size_t)E3 * EE];
__device__ __half g_outw16[(size_t)EE * EE];
__device__ __half g_w116[(size_t)DFF * EE];
__device__ __half g_w216[(size_t)EE * DFF];

// ---------------------------------------------------------------------------
// helpers
// ---------------------------------------------------------------------------
__device__ __forceinline__ uint32_t smem_u32(const void* p) {
    uint32_t a;
    asm("{ .reg .u64 t; cvta.to.shared.u64 t, %1; cvt.u32.u64 %0, t; }"
        : "=r"(a) : "l"(p));
    return a;
}
__device__ __forceinline__ void cpasync16(uint32_t s, const void* g) {
    asm volatile("cp.async.cg.shared.global [%0], [%1], 16;" :: "r"(s), "l"(g));
}
__device__ __forceinline__ void ldsm4(uint32_t r[4], uint32_t addr) {
    asm volatile("ldmatrix.sync.aligned.m8n8.x4.shared.b16 {%0,%1,%2,%3}, [%4];"
                 : "=r"(r[0]), "=r"(r[1]), "=r"(r[2]), "=r"(r[3]) : "r"(addr));
}
__device__ __forceinline__ void ldsm4t(uint32_t r[4], uint32_t addr) {
    asm volatile("ldmatrix.sync.aligned.m8n8.x4.trans.shared.b16 {%0,%1,%2,%3}, [%4];"
                 : "=r"(r[0]), "=r"(r[1]), "=r"(r[2]), "=r"(r[3]) : "r"(addr));
}
__device__ __forceinline__ void mma16816(float c[4], const uint32_t a[4],
                                         uint32_t b0, uint32_t b1) {
    asm volatile(
        "mma.sync.aligned.m16n8k16.row.col.f32.f16.f16.f32 "
        "{%0,%1,%2,%3}, {%4,%5,%6,%7}, {%8,%9}, {%0,%1,%2,%3};"
        : "+f"(c[0]), "+f"(c[1]), "+f"(c[2]), "+f"(c[3])
        : "r"(a[0]), "r"(a[1]), "r"(a[2]), "r"(a[3]), "r"(b0), "r"(b1));
}
__device__ __forceinline__ uint32_t packh2(float x, float y) {
    __half2 h = __floats2half2_rn(x, y);
    return *reinterpret_cast<uint32_t*>(&h);
}

// ---------------------------------------------------------------------------
// fp32 -> fp16 convert (weights + src, one-time per launch)
// ---------------------------------------------------------------------------
__global__ __launch_bounds__(256)
void cvt_kernel(const float* __restrict__ in, __half* __restrict__ o, int n4)
{
    int i = blockIdx.x * blockDim.x + threadIdx.x;
    if (i >= n4) return;
    float4 v = ((const float4*)in)[i];
    uint2 p;
    p.x = packh2(v.x, v.y);
    p.y = packh2(v.z, v.w);
    ((uint2*)o)[i] = p;
}

// ---------------------------------------------------------------------------
// Tensor-core GEMM, fp16 single-pass: C = A[M,K] @ B[N,K]^T + bias
// CTA 128x128, BK=32, 256 threads (8 warps, warp tile 32x64).
// cp.async 2-stage pipeline; smem rows 64B data + 16B pad (80B stride).
// EPI: 0 = bias -> fp32 C;  1 = bias+relu -> fp16 C16;  2 = bias -> fp16 C16
// ---------------------------------------------------------------------------
#define TSTRIDE 80
#define PLANE   (128 * TSTRIDE)          // 10240 B
#define STAGE   (2 * PLANE)              // A, B = 20480 B
#define GSMEM   (2 * STAGE)              // 40960 B

template <int EPI>
__global__ __launch_bounds__(256, 2)
void gemm_mma(const __half* __restrict__ Ag, const __half* __restrict__ Bg,
              const float* __restrict__ bias,
              float* __restrict__ C, __half* __restrict__ C16,
              int Ndim, int Kdim)
{
    extern __shared__ char sm[];
    const int t    = threadIdx.x;
    const int lane = t & 31;
    const int wid  = t >> 5;
    const int wm   = (wid & 3) * 32;
    const int wn   = (wid >> 2) * 64;
    const int bm   = blockIdx.y * 128;
    const int bn   = blockIdx.x * 128;

    const uint32_t smb = smem_u32(sm);

    auto issue = [&](int k0, int buf) {
        uint32_t sb = smb + buf * STAGE;
#pragma unroll
        for (int i = 0; i < 2; i++) {
            int e = t + i * 256;
            int r = e >> 2, c = e & 3;
            uint32_t off = (uint32_t)(r * TSTRIDE + c * 16);
            size_t ga = (size_t)(bm + r) * Kdim + k0 + c * 8;
            size_t gb = (size_t)(bn + r) * Kdim + k0 + c * 8;
            cpasync16(sb + off,         Ag + ga);
            cpasync16(sb + PLANE + off, Bg + gb);
        }
        asm volatile("cp.async.commit_group;");
    };

    float acc[2][8][4];
#pragma unroll
    for (int i = 0; i < 2; i++)
#pragma unroll
        for (int j = 0; j < 8; j++)
#pragma unroll
            for (int k = 0; k < 4; k++) acc[i][j][k] = 0.0f;

    const int kc = Kdim / 32;
    issue(0, 0);

    for (int ic = 0; ic < kc; ic++) {
        const int buf = ic & 1;
        if (ic + 1 < kc) {
            issue((ic + 1) * 32, buf ^ 1);
            asm volatile("cp.async.wait_group 1;");
        } else {
            asm volatile("cp.async.wait_group 0;");
        }
        __syncthreads();

        const uint32_t pA = smb + buf * STAGE;
        const uint32_t pB = pA + PLANE;

#pragma unroll
        for (int ks = 0; ks < 2; ks++) {
            uint32_t Af[2][4];
#pragma unroll
            for (int i = 0; i < 2; i++) {
                uint32_t off = (uint32_t)((wm + i * 16 + (lane & 15)) * TSTRIDE
                               + ks * 32 + ((lane >> 4) << 4));
                ldsm4(Af[i], pA + off);
            }
#pragma unroll
            for (int bh2 = 0; bh2 < 2; bh2++) {
                uint32_t Bf[2][4];
#pragma unroll
                for (int g = 0; g < 2; g++) {
                    int nb = wn + bh2 * 32 + g * 16;
                    uint32_t off = (uint32_t)((nb + (lane & 7) + ((lane >> 4) << 3)) * TSTRIDE
                                   + ks * 32 + (((lane >> 3) & 1) << 4));
                    ldsm4(Bf[g], pB + off);
                }
#pragma unroll
                for (int g = 0; g < 2; g++)
#pragma unroll
                    for (int jj = 0; jj < 2; jj++) {
                        int j = bh2 * 4 + g * 2 + jj;
#pragma unroll
                        for (int i = 0; i < 2; i++)
                            mma16816(acc[i][j], Af[i], Bf[g][jj * 2], Bf[g][jj * 2 + 1]);
                    }
            }
        }
        __syncthreads();
    }

#pragma unroll
    for (int i = 0; i < 2; i++) {
        const int r0 = bm + wm + i * 16 + (lane >> 2);
#pragma unroll
        for (int j = 0; j < 8; j++) {
            const int c = bn + wn + j * 8 + 2 * (lane & 3);
            const float bx = bias[c], by = bias[c + 1];
            float v0x = acc[i][j][0] + bx, v0y = acc[i][j][1] + by;
            float v1x = acc[i][j][2] + bx, v1y = acc[i][j][3] + by;
            if (EPI == 0) {
                *(float2*)(C + (size_t)r0 * Ndim + c)       = make_float2(v0x, v0y);
                *(float2*)(C + (size_t)(r0 + 8) * Ndim + c) = make_float2(v1x, v1y);
            } else {
                if (EPI == 1) {
                    v0x = fmaxf(v0x, 0.f); v0y = fmaxf(v0y, 0.f);
                    v1x = fmaxf(v1x, 0.f); v1y = fmaxf(v1y, 0.f);
                }
                *(uint32_t*)(C16 + (size_t)r0 * Ndim + c)       = packh2(v0x, v0y);
                *(uint32_t*)(C16 + (size_t)(r0 + 8) * Ndim + c) = packh2(v1x, v1y);
            }
        }
    }
}

// ---------------------------------------------------------------------------
// Flash attention via mma.sync fp16
// ---------------------------------------------------------------------------
#define ATS 144
#define ATILE (64 * ATS)

__global__ __launch_bounds__(128)
void attn_mma(const __half* __restrict__ qkv, __half* __restrict__ ctx)
{
    __shared__ __align__(16) char smQ[ATILE];
    __shared__ __align__(16) char smK[2][ATILE];
    __shared__ __align__(16) char smV[2][ATILE];

    const int qt = blockIdx.x & 15;
    const int bh = blockIdx.x >> 4;
    const int b  = bh / HH;
    const int h  = bh % HH;
    const int t  = threadIdx.x;
    const int lane = t & 31;
    const int w  = t >> 5;
    const int q0 = w * 16;

    const size_t rowstride = (size_t)BB * E3;
    const __half* Qg = qkv + ((size_t)(qt * 64) * BB + b) * E3 + h * DD;
    const __half* Kg = qkv + (size_t)b * E3 + EE + h * DD;
    const __half* Vg = Kg + EE;

    const uint32_t uQ = smem_u32(smQ);
    const uint32_t uK = smem_u32(smK[0]);
    const uint32_t uV = smem_u32(smV[0]);

    auto issue_kv = [&](int kt, int buf) {
#pragma unroll
        for (int i = 0; i < 4; i++) {
            int e = t + i * 128;
            int r = e >> 3, c = e & 7;
            uint32_t off = (uint32_t)(r * ATS + c * 16) + (uint32_t)(buf * ATILE);
            size_t g = (size_t)(kt * 64 + r) * rowstride + c * 8;
            cpasync16(uK + off, Kg + g);
            cpasync16(uV + off, Vg + g);
        }
        asm volatile("cp.async.commit_group;");
    };

#pragma unroll
    for (int i = 0; i < 4; i++) {
        int e = t + i * 128;
        int r = e >> 3, c = e & 7;
        uint32_t off = (uint32_t)(r * ATS + c * 16);
        size_t g = (size_t)r * rowstride + c * 8;
        cpasync16(uQ + off, Qg + g);
        cpasync16(uK + off, Kg + g);
        cpasync16(uV + off, Vg + g);
    }
    asm volatile("cp.async.commit_group;");

    uint32_t Aq[4][4];
    float oacc[8][4];
#pragma unroll
    for (int j = 0; j < 8; j++)
#pragma unroll
        for (int e = 0; e < 4; e++) oacc[j][e] = 0.0f;
    float m0 = -1e30f, m1 = -1e30f, l0 = 0.0f, l1 = 0.0f;

    for (int kt = 0; kt < 16; kt++) {
        const int buf = kt & 1;
        if (kt + 1 < 16) {
            issue_kv(kt + 1, buf ^ 1);
            asm volatile("cp.async.wait_group 1;");
        } else {
            asm volatile("cp.async.wait_group 0;");
        }
        __syncthreads();

        if (kt == 0) {
#pragma unroll
            for (int ks = 0; ks < 4; ks++) {
                uint32_t off = (uint32_t)((q0 + (lane & 15)) * ATS + ks * 32 + ((lane >> 4) << 4));
                ldsm4(Aq[ks], uQ + off);
            }
        }
        const uint32_t pK = uK + buf * ATILE;
        const uint32_t pV = uV + buf * ATILE;

        float sacc[8][4];
#pragma unroll
        for (int j = 0; j < 8; j++)
#pragma unroll
            for (int e = 0; e < 4; e++) sacc[j][e] = 0.0f;
#pragma unroll
        for (int ks = 0; ks < 4; ks++) {
#pragma unroll
            for (int g = 0; g < 4; g++) {
                uint32_t Kf[4];
                uint32_t off = (uint32_t)((g * 16 + (lane & 7) + ((lane >> 4) << 3)) * ATS
                               + ks * 32 + (((lane >> 3) & 1) << 4));
                ldsm4(Kf, pK + off);
                mma16816(sacc[g * 2],     Aq[ks], Kf[0], Kf[1]);
                mma16816(sacc[g * 2 + 1], Aq[ks], Kf[2], Kf[3]);
            }
        }

        float mx0 = -1e30f, mx1 = -1e30f;
#pragma unroll
        for (int j = 0; j < 8; j++) {
            sacc[j][0] *= 0.125f; sacc[j][1] *= 0.125f;
            sacc[j][2] *= 0.125f; sacc[j][3] *= 0.125f;
            mx0 = fmaxf(mx0, fmaxf(sacc[j][0], sacc[j][1]));
            mx1 = fmaxf(mx1, fmaxf(sacc[j][2], sacc[j][3]));
        }
        mx0 = fmaxf(mx0, __shfl_xor_sync(0xffffffffu, mx0, 1));
        mx0 = fmaxf(mx0, __shfl_xor_sync(0xffffffffu, mx0, 2));
        mx1 = fmaxf(mx1, __shfl_xor_sync(0xffffffffu, mx1, 1));
        mx1 = fmaxf(mx1, __shfl_xor_sync(0xffffffffu, mx1, 2));

        float nm0 = fmaxf(m0, mx0), nm1 = fmaxf(m1, mx1);
        float c0 = __expf(m0 - nm0), c1 = __expf(m1 - nm1);

        float s0 = 0.0f, s1 = 0.0f;
        uint32_t Pa[4][4];
#pragma unroll
        for (int j = 0; j < 8; j++) {
            float p0 = __expf(sacc[j][0] - nm0);
            float p1 = __expf(sacc[j][1] - nm0);
            float p2 = __expf(sacc[j][2] - nm1);
            float p3 = __expf(sacc[j][3] - nm1);
            s0 += p0 + p1; s1 += p2 + p3;
            const int ks = j >> 1, hi = j & 1;
            Pa[ks][hi * 2]     = packh2(p0, p1);
            Pa[ks][hi * 2 + 1] = packh2(p2, p3);
        }
        s0 += __shfl_xor_sync(0xffffffffu, s0, 1);
        s0 += __shfl_xor_sync(0xffffffffu, s0, 2);
        s1 += __shfl_xor_sync(0xffffffffu, s1, 1);
        s1 += __shfl_xor_sync(0xffffffffu, s1, 2);

        l0 = l0 * c0 + s0;  l1 = l1 * c1 + s1;
        m0 = nm0;           m1 = nm1;
#pragma unroll
        for (int j = 0; j < 8; j++) {
            oacc[j][0] *= c0; oacc[j][1] *= c0;
            oacc[j][2] *= c1; oacc[j][3] *= c1;
        }

#pragma unroll
        for (int ks = 0; ks < 4; ks++) {
#pragma unroll
            for (int dg = 0; dg < 4; dg++) {
                uint32_t Vf[4];
                uint32_t off = (uint32_t)((ks * 16 + (lane & 7) + (((lane >> 3) & 1) << 3)) * ATS
                               + dg * 32 + ((lane >> 4) << 4));
                ldsm4t(Vf, pV + off);
                mma16816(oacc[dg * 2],     Pa[ks], Vf[0], Vf[1]);
                mma16816(oacc[dg * 2 + 1], Pa[ks], Vf[2], Vf[3]);
            }
        }
        __syncthreads();
    }

    const float i0 = 1.0f / l0, i1 = 1.0f / l1;
    const int r0 = qt * 64 + q0 + (lane >> 2);
#pragma unroll
    for (int j = 0; j < 8; j++) {
        const int col = h * DD + j * 8 + 2 * (lane & 3);
        *(uint32_t*)(ctx + ((size_t)r0 * BB + b) * EE + col) =
            packh2(oacc[j][0] * i0, oacc[j][1] * i0);
        *(uint32_t*)(ctx + ((size_t)(r0 + 8) * BB + b) * EE + col) =
            packh2(oacc[j][2] * i1, oacc[j][3] * i1);
    }
}

// ---------------------------------------------------------------------------
// out = layernorm(a + b) * g + beta; CVT=1 also writes fp16 plane
// ---------------------------------------------------------------------------
template <int CVT>
__global__ __launch_bounds__(256)
void add_ln_kernel(const float* __restrict__ a, const float* __restrict__ bres,
                   const float* __restrict__ g, const float* __restrict__ beta,
                   float* __restrict__ out, __half* __restrict__ o16)
{
    const int row = blockIdx.x;
    const int t   = threadIdx.x;
    const float4* A4 = (const float4*)(a    + (size_t)row * EE);
    const float4* B4 = (const float4*)(bres + (size_t)row * EE);

    float4 x = A4[t];
    float4 y = B4[t];
    x.x += y.x; x.y += y.y; x.z += y.z; x.w += y.w;

    float s  = x.x + x.y + x.z + x.w;
    float ss = x.x * x.x + x.y * x.y + x.z * x.z + x.w * x.w;

#pragma unroll
    for (int off = 16; off > 0; off >>= 1) {
        s  += __shfl_xor_sync(0xffffffffu, s,  off);
        ss += __shfl_xor_sync(0xffffffffu, ss, off);
    }
    __shared__ float sh_s[8], sh_ss[8];
    const int w = t >> 5, l = t & 31;
    if (l == 0) { sh_s[w] = s; sh_ss[w] = ss; }
    __syncthreads();
    s = 0.0f; ss = 0.0f;
#pragma unroll
    for (int i = 0; i < 8; i++) { s += sh_s[i]; ss += sh_ss[i]; }

    const float mean = s * (1.0f / EE);
    const float var  = ss * (1.0f / EE) - mean * mean;
    const float rstd = rsqrtf(var + 1e-5f);

    float4 g4 = ((const float4*)g)[t];
    float4 b4 = ((const float4*)beta)[t];
    float4 o;
    o.x = (x.x - mean) * rstd * g4.x + b4.x;
    o.y = (x.y - mean) * rstd * g4.y + b4.y;
    o.z = (x.z - mean) * rstd * g4.z + b4.z;
    o.w = (x.w - mean) * rstd * g4.w + b4.w;
    ((float4*)(out + (size_t)row * EE))[t] = o;

    if (CVT) {
        uint2 p;
        p.x = packh2(o.x, o.y);
        p.y = packh2(o.z, o.w);
        ((uint2*)(o16 + (size_t)row * EE))[t] = p;
    }
}

// ---------------------------------------------------------------------------
// launch
// ---------------------------------------------------------------------------
extern "C" void kernel_launch(void* const* d_in, const int* in_sizes, int n_in,
                              void* d_out, int out_size)
{
    const float* src    = (const float*)d_in[0];
    const float* in_w   = (const float*)d_in[1];
    const float* in_b   = (const float*)d_in[2];
    const float* out_w  = (const float*)d_in[3];
    const float* out_b  = (const float*)d_in[4];
    const float* ln1g   = (const float*)d_in[5];
    const float* ln1b   = (const float*)d_in[6];
    const float* ln2g   = (const float*)d_in[7];
    const float* ln2b   = (const float*)d_in[8];
    const float* w1     = (const float*)d_in[9];
    const float* b1     = (const float*)d_in[10];
    const float* w2     = (const float*)d_in[11];
    const float* b2     = (const float*)d_in[12];
    float* out = (float*)d_out;

    float *tmp, *x;
    cudaGetSymbolAddress((void**)&tmp, g_tmp);
    cudaGetSymbolAddress((void**)&x,   g_x);

    __half *qkv16, *src16, *ctx16, *x16, *ff116;
    __half *inw16, *outw16, *w116, *w216;
    cudaGetSymbolAddress((void**)&qkv16, g_qkv16);
    cudaGetSymbolAddress((void**)&src16, g_src16);
    cudaGetSymbolAddress((void**)&ctx16, g_ctx16);
    cudaGetSymbolAddress((void**)&x16,   g_x16);
    cudaGetSymbolAddress((void**)&ff116, g_ff116);
    cudaGetSymbolAddress((void**)&inw16,  g_inw16);
    cudaGetSymbolAddress((void**)&outw16, g_outw16);
    cudaGetSymbolAddress((void**)&w116,   g_w116);
    cudaGetSymbolAddress((void**)&w216,   g_w216);

    cudaFuncSetAttribute(gemm_mma<0>, cudaFuncAttributeMaxDynamicSharedMemorySize, GSMEM);
    cudaFuncSetAttribute(gemm_mma<1>, cudaFuncAttributeMaxDynamicSharedMemorySize, GSMEM);
    cudaFuncSetAttribute(gemm_mma<2>, cudaFuncAttributeMaxDynamicSharedMemorySize, GSMEM);

    // 0. one-time fp16 converts (weights + src)
    auto cvt = [&](const float* p, __half* o, size_t n) {
        int n4 = (int)(n / 4);
        cvt_kernel<<<(n4 + 255) / 256, 256>>>(p, o, n4);
    };
    cvt(in_w,  inw16,  (size_t)E3 * EE);
    cvt(out_w, outw16, (size_t)EE * EE);
    cvt(w1,    w116,   (size_t)DFF * EE);
    cvt(w2,    w216,   (size_t)EE * DFF);
    cvt(src,   src16,  (size_t)MTOK * EE);

    // 1. qkv = src @ in_proj_w^T + b        (8192 x 3072 x 1024) -> fp16
    gemm_mma<2><<<dim3(E3 / 128, MTOK / 128), 256, GSMEM>>>(
        src16, inw16, in_b, nullptr, qkv16, E3, EE);
    // 2. flash attention (mma.sync fp16) -> ctx fp16
    attn_mma<<<BB * HH * 16, 128>>>(qkv16, ctx16);
    // 3. attn_out = ctx @ out_w^T + out_b   (8192 x 1024 x 1024) -> fp32 tmp
    gemm_mma<0><<<dim3(EE / 128, MTOK / 128), 256, GSMEM>>>(
        ctx16, outw16, out_b, tmp, nullptr, EE, EE);
    // 4. x = LN1(src + attn_out) -> fp32 x + fp16 x16
    add_ln_kernel<1><<<MTOK, 256>>>(src, tmp, ln1g, ln1b, x, x16);
    // 5. ff1 = relu(x @ w1^T + b1)          (8192 x 4096 x 1024) -> fp16
    gemm_mma<1><<<dim3(DFF / 128, MTOK / 128), 256, GSMEM>>>(
        x16, w116, b1, nullptr, ff116, DFF, EE);
    // 6. ff2 = ff1 @ w2^T + b2              (8192 x 1024 x 4096) -> fp32 tmp
    gemm_mma<0><<<dim3(EE / 128, MTOK / 128), 256, GSMEM>>>(
        ff116, w216, b2, tmp, nullptr, EE, DFF);
    // 7. out = LN2(x + ff2)
    add_ln_kernel<0><<<MTOK, 256>>>(x, tmp, ln2g, ln2b, out, nullptr);
}

// round 15
// speedup vs baseline: 9.2857x; 1.1141x over previous
#include <cuda_runtime.h>
#include <cuda_fp16.h>
#include <cstdint>
#include <cstddef>

// Problem constants
#define SQ   1024
#define BB   8
#define EE   1024
#define HH   16
#define DD   64
#define DFF  4096
#define MTOK (SQ * BB)     // 8192
#define E3   (3 * EE)      // 3072

// ---------------------------------------------------------------------------
// Scratch (__device__ globals; no allocations allowed)
// ---------------------------------------------------------------------------
__device__ float g_x[(size_t)MTOK * EE];

// fp16 single-plane activations
__device__ __half g_qkv16[(size_t)MTOK * E3];
__device__ __half g_src16[(size_t)MTOK * EE];
__device__ __half g_ctx16[(size_t)MTOK * EE];
__device__ __half g_x16  [(size_t)MTOK * EE];
__device__ __half g_ff116[(size_t)MTOK * DFF];
__device__ __half g_tmp16[(size_t)MTOK * EE];

// fp16 weights (single plane)
__device__ __half g_inw16[(size_t)E3 * EE];
__device__ __half g_outw16[(size_t)EE * EE];
__device__ __half g_w116[(size_t)DFF * EE];
__device__ __half g_w216[(size_t)EE * DFF];

// ---------------------------------------------------------------------------
// helpers
// ---------------------------------------------------------------------------
__device__ __forceinline__ uint32_t smem_u32(const void* p) {
    uint32_t a;
    asm("{ .reg .u64 t; cvta.to.shared.u64 t, %1; cvt.u32.u64 %0, t; }"
        : "=r"(a) : "l"(p));
    return a;
}
__device__ __forceinline__ void cpasync16(uint32_t s, const void* g) {
    asm volatile("cp.async.cg.shared.global [%0], [%1], 16;" :: "r"(s), "l"(g));
}
__device__ __forceinline__ void ldsm4(uint32_t r[4], uint32_t addr) {
    asm volatile("ldmatrix.sync.aligned.m8n8.x4.shared.b16 {%0,%1,%2,%3}, [%4];"
                 : "=r"(r[0]), "=r"(r[1]), "=r"(r[2]), "=r"(r[3]) : "r"(addr));
}
__device__ __forceinline__ void ldsm4t(uint32_t r[4], uint32_t addr) {
    asm volatile("ldmatrix.sync.aligned.m8n8.x4.trans.shared.b16 {%0,%1,%2,%3}, [%4];"
                 : "=r"(r[0]), "=r"(r[1]), "=r"(r[2]), "=r"(r[3]) : "r"(addr));
}
__device__ __forceinline__ void mma16816(float c[4], const uint32_t a[4],
                                         uint32_t b0, uint32_t b1) {
    asm volatile(
        "mma.sync.aligned.m16n8k16.row.col.f32.f16.f16.f32 "
        "{%0,%1,%2,%3}, {%4,%5,%6,%7}, {%8,%9}, {%0,%1,%2,%3};"
        : "+f"(c[0]), "+f"(c[1]), "+f"(c[2]), "+f"(c[3])
        : "r"(a[0]), "r"(a[1]), "r"(a[2]), "r"(a[3]), "r"(b0), "r"(b1));
}
__device__ __forceinline__ uint32_t packh2(float x, float y) {
    __half2 h = __floats2half2_rn(x, y);
    return *reinterpret_cast<uint32_t*>(&h);
}

// ---------------------------------------------------------------------------
// fp32 -> fp16 convert (weights + src, one-time per launch)
// ---------------------------------------------------------------------------
__global__ __launch_bounds__(256)
void cvt_kernel(const float* __restrict__ in, __half* __restrict__ o, int n4)
{
    int i = blockIdx.x * blockDim.x + threadIdx.x;
    if (i >= n4) return;
    float4 v = ((const float4*)in)[i];
    uint2 p;
    p.x = packh2(v.x, v.y);
    p.y = packh2(v.z, v.w);
    ((uint2*)o)[i] = p;
}

// ---------------------------------------------------------------------------
// Tensor-core GEMM, fp16 single-pass: C = A[M,K] @ B[N,K]^T + bias
// CTA 128x128, BK=64, 256 threads (8 warps, warp tile 32x64).
// cp.async 2-stage pipeline; smem rows 128B data + 16B pad (144B stride).
// EPI: 1 = bias+relu -> fp16 C16;  2 = bias -> fp16 C16
// ---------------------------------------------------------------------------
#define TSTRIDE 144
#define PLANE   (128 * TSTRIDE)          // 18432 B
#define STAGE   (2 * PLANE)              // A, B = 36864 B
#define GSMEM   (2 * STAGE)              // 73728 B

template <int EPI>
__global__ __launch_bounds__(256, 2)
void gemm_mma(const __half* __restrict__ Ag, const __half* __restrict__ Bg,
              const float* __restrict__ bias,
              __half* __restrict__ C16,
              int Ndim, int Kdim)
{
    extern __shared__ char sm[];
    const int t    = threadIdx.x;
    const int lane = t & 31;
    const int wid  = t >> 5;
    const int wm   = (wid & 3) * 32;
    const int wn   = (wid >> 2) * 64;
    const int bm   = blockIdx.y * 128;
    const int bn   = blockIdx.x * 128;

    const uint32_t smb = smem_u32(sm);

    auto issue = [&](int k0, int buf) {
        uint32_t sb = smb + buf * STAGE;
#pragma unroll
        for (int i = 0; i < 4; i++) {
            int e = t + i * 256;                  // 0..1023
            int r = e >> 3, c = e & 7;            // r 0..127, c 0..7 (16B units)
            uint32_t off = (uint32_t)(r * TSTRIDE + c * 16);
            size_t ga = (size_t)(bm + r) * Kdim + k0 + c * 8;
            size_t gb = (size_t)(bn + r) * Kdim + k0 + c * 8;
            cpasync16(sb + off,         Ag + ga);
            cpasync16(sb + PLANE + off, Bg + gb);
        }
        asm volatile("cp.async.commit_group;");
    };

    float acc[2][8][4];
#pragma unroll
    for (int i = 0; i < 2; i++)
#pragma unroll
        for (int j = 0; j < 8; j++)
#pragma unroll
            for (int k = 0; k < 4; k++) acc[i][j][k] = 0.0f;

    const int kc = Kdim / 64;
    issue(0, 0);

    for (int ic = 0; ic < kc; ic++) {
        const int buf = ic & 1;
        if (ic + 1 < kc) {
            issue((ic + 1) * 64, buf ^ 1);
            asm volatile("cp.async.wait_group 1;");
        } else {
            asm volatile("cp.async.wait_group 0;");
        }
        __syncthreads();

        const uint32_t pA = smb + buf * STAGE;
        const uint32_t pB = pA + PLANE;

#pragma unroll
        for (int ks = 0; ks < 4; ks++) {
            uint32_t Af[2][4];
#pragma unroll
            for (int i = 0; i < 2; i++) {
                uint32_t off = (uint32_t)((wm + i * 16 + (lane & 15)) * TSTRIDE
                               + ks * 32 + ((lane >> 4) << 4));
                ldsm4(Af[i], pA + off);
            }
#pragma unroll
            for (int bh2 = 0; bh2 < 2; bh2++) {
                uint32_t Bf[2][4];
#pragma unroll
                for (int g = 0; g < 2; g++) {
                    int nb = wn + bh2 * 32 + g * 16;
                    uint32_t off = (uint32_t)((nb + (lane & 7) + ((lane >> 4) << 3)) * TSTRIDE
                                   + ks * 32 + (((lane >> 3) & 1) << 4));
                    ldsm4(Bf[g], pB + off);
                }
#pragma unroll
                for (int g = 0; g < 2; g++)
#pragma unroll
                    for (int jj = 0; jj < 2; jj++) {
                        int j = bh2 * 4 + g * 2 + jj;
#pragma unroll
                        for (int i = 0; i < 2; i++)
                            mma16816(acc[i][j], Af[i], Bf[g][jj * 2], Bf[g][jj * 2 + 1]);
                    }
            }
        }
        __syncthreads();
    }

#pragma unroll
    for (int i = 0; i < 2; i++) {
        const int r0 = bm + wm + i * 16 + (lane >> 2);
#pragma unroll
        for (int j = 0; j < 8; j++) {
            const int c = bn + wn + j * 8 + 2 * (lane & 3);
            const float bx = bias[c], by = bias[c + 1];
            float v0x = acc[i][j][0] + bx, v0y = acc[i][j][1] + by;
            float v1x = acc[i][j][2] + bx, v1y = acc[i][j][3] + by;
            if (EPI == 1) {
                v0x = fmaxf(v0x, 0.f); v0y = fmaxf(v0y, 0.f);
                v1x = fmaxf(v1x, 0.f); v1y = fmaxf(v1y, 0.f);
            }
            *(uint32_t*)(C16 + (size_t)r0 * Ndim + c)       = packh2(v0x, v0y);
            *(uint32_t*)(C16 + (size_t)(r0 + 8) * Ndim + c) = packh2(v1x, v1y);
        }
    }
}

// ---------------------------------------------------------------------------
// Flash attention via mma.sync fp16
// ---------------------------------------------------------------------------
#define ATS 144
#define ATILE (64 * ATS)

__global__ __launch_bounds__(128)
void attn_mma(const __half* __restrict__ qkv, __half* __restrict__ ctx)
{
    __shared__ __align__(16) char smQ[ATILE];
    __shared__ __align__(16) char smK[2][ATILE];
    __shared__ __align__(16) char smV[2][ATILE];

    const int qt = blockIdx.x & 15;
    const int bh = blockIdx.x >> 4;
    const int b  = bh / HH;
    const int h  = bh % HH;
    const int t  = threadIdx.x;
    const int lane = t & 31;
    const int w  = t >> 5;
    const int q0 = w * 16;

    const size_t rowstride = (size_t)BB * E3;
    const __half* Qg = qkv + ((size_t)(qt * 64) * BB + b) * E3 + h * DD;
    const __half* Kg = qkv + (size_t)b * E3 + EE + h * DD;
    const __half* Vg = Kg + EE;

    const uint32_t uQ = smem_u32(smQ);
    const uint32_t uK = smem_u32(smK[0]);
    const uint32_t uV = smem_u32(smV[0]);

    auto issue_kv = [&](int kt, int buf) {
#pragma unroll
        for (int i = 0; i < 4; i++) {
            int e = t + i * 128;
            int r = e >> 3, c = e & 7;
            uint32_t off = (uint32_t)(r * ATS + c * 16) + (uint32_t)(buf * ATILE);
            size_t g = (size_t)(kt * 64 + r) * rowstride + c * 8;
            cpasync16(uK + off, Kg + g);
            cpasync16(uV + off, Vg + g);
        }
        asm volatile("cp.async.commit_group;");
    };

#pragma unroll
    for (int i = 0; i < 4; i++) {
        int e = t + i * 128;
        int r = e >> 3, c = e & 7;
        uint32_t off = (uint32_t)(r * ATS + c * 16);
        size_t g = (size_t)r * rowstride + c * 8;
        cpasync16(uQ + off, Qg + g);
        cpasync16(uK + off, Kg + g);
        cpasync16(uV + off, Vg + g);
    }
    asm volatile("cp.async.commit_group;");

    uint32_t Aq[4][4];
    float oacc[8][4];
#pragma unroll
    for (int j = 0; j < 8; j++)
#pragma unroll
        for (int e = 0; e < 4; e++) oacc[j][e] = 0.0f;
    float m0 = -1e30f, m1 = -1e30f, l0 = 0.0f, l1 = 0.0f;

    for (int kt = 0; kt < 16; kt++) {
        const int buf = kt & 1;
        if (kt + 1 < 16) {
            issue_kv(kt + 1, buf ^ 1);
            asm volatile("cp.async.wait_group 1;");
        } else {
            asm volatile("cp.async.wait_group 0;");
        }
        __syncthreads();

        if (kt == 0) {
#pragma unroll
            for (int ks = 0; ks < 4; ks++) {
                uint32_t off = (uint32_t)((q0 + (lane & 15)) * ATS + ks * 32 + ((lane >> 4) << 4));
                ldsm4(Aq[ks], uQ + off);
            }
        }
        const uint32_t pK = uK + buf * ATILE;
        const uint32_t pV = uV + buf * ATILE;

        float sacc[8][4];
#pragma unroll
        for (int j = 0; j < 8; j++)
#pragma unroll
            for (int e = 0; e < 4; e++) sacc[j][e] = 0.0f;
#pragma unroll
        for (int ks = 0; ks < 4; ks++) {
#pragma unroll
            for (int g = 0; g < 4; g++) {
                uint32_t Kf[4];
                uint32_t off = (uint32_t)((g * 16 + (lane & 7) + ((lane >> 4) << 3)) * ATS
                               + ks * 32 + (((lane >> 3) & 1) << 4));
                ldsm4(Kf, pK + off);
                mma16816(sacc[g * 2],     Aq[ks], Kf[0], Kf[1]);
                mma16816(sacc[g * 2 + 1], Aq[ks], Kf[2], Kf[3]);
            }
        }

        float mx0 = -1e30f, mx1 = -1e30f;
#pragma unroll
        for (int j = 0; j < 8; j++) {
            sacc[j][0] *= 0.125f; sacc[j][1] *= 0.125f;
            sacc[j][2] *= 0.125f; sacc[j][3] *= 0.125f;
            mx0 = fmaxf(mx0, fmaxf(sacc[j][0], sacc[j][1]));
            mx1 = fmaxf(mx1, fmaxf(sacc[j][2], sacc[j][3]));
        }
        mx0 = fmaxf(mx0, __shfl_xor_sync(0xffffffffu, mx0, 1));
        mx0 = fmaxf(mx0, __shfl_xor_sync(0xffffffffu, mx0, 2));
        mx1 = fmaxf(mx1, __shfl_xor_sync(0xffffffffu, mx1, 1));
        mx1 = fmaxf(mx1, __shfl_xor_sync(0xffffffffu, mx1, 2));

        float nm0 = fmaxf(m0, mx0), nm1 = fmaxf(m1, mx1);
        float c0 = __expf(m0 - nm0), c1 = __expf(m1 - nm1);

        float s0 = 0.0f, s1 = 0.0f;
        uint32_t Pa[4][4];
#pragma unroll
        for (int j = 0; j < 8; j++) {
            float p0 = __expf(sacc[j][0] - nm0);
            float p1 = __expf(sacc[j][1] - nm0);
            float p2 = __expf(sacc[j][2] - nm1);
            float p3 = __expf(sacc[j][3] - nm1);
            s0 += p0 + p1; s1 += p2 + p3;
            const int ks = j >> 1, hi = j & 1;
            Pa[ks][hi * 2]     = packh2(p0, p1);
            Pa[ks][hi * 2 + 1] = packh2(p2, p3);
        }
        s0 += __shfl_xor_sync(0xffffffffu, s0, 1);
        s0 += __shfl_xor_sync(0xffffffffu, s0, 2);
        s1 += __shfl_xor_sync(0xffffffffu, s1, 1);
        s1 += __shfl_xor_sync(0xffffffffu, s1, 2);

        l0 = l0 * c0 + s0;  l1 = l1 * c1 + s1;
        m0 = nm0;           m1 = nm1;
#pragma unroll
        for (int j = 0; j < 8; j++) {
            oacc[j][0] *= c0; oacc[j][1] *= c0;
            oacc[j][2] *= c1; oacc[j][3] *= c1;
        }

#pragma unroll
        for (int ks = 0; ks < 4; ks++) {
#pragma unroll
            for (int dg = 0; dg < 4; dg++) {
                uint32_t Vf[4];
                uint32_t off = (uint32_t)((ks * 16 + (lane & 7) + (((lane >> 3) & 1) << 3)) * ATS
                               + dg * 32 + ((lane >> 4) << 4));
                ldsm4t(Vf, pV + off);
                mma16816(oacc[dg * 2],     Pa[ks], Vf[0], Vf[1]);
                mma16816(oacc[dg * 2 + 1], Pa[ks], Vf[2], Vf[3]);
            }
        }
        __syncthreads();
    }

    const float i0 = 1.0f / l0, i1 = 1.0f / l1;
    const int r0 = qt * 64 + q0 + (lane >> 2);
#pragma unroll
    for (int j = 0; j < 8; j++) {
        const int col = h * DD + j * 8 + 2 * (lane & 3);
        *(uint32_t*)(ctx + ((size_t)r0 * BB + b) * EE + col) =
            packh2(oacc[j][0] * i0, oacc[j][1] * i0);
        *(uint32_t*)(ctx + ((size_t)(r0 + 8) * BB + b) * EE + col) =
            packh2(oacc[j][2] * i1, oacc[j][3] * i1);
    }
}

// ---------------------------------------------------------------------------
// out = layernorm(a + bres16) * g + beta; residual read as fp16.
// CVT=1 also writes fp16 plane.
// ---------------------------------------------------------------------------
template <int CVT>
__global__ __launch_bounds__(256)
void add_ln_kernel(const float* __restrict__ a, const __half* __restrict__ bres16,
                   const float* __restrict__ g, const float* __restrict__ beta,
                   float* __restrict__ out, __half* __restrict__ o16)
{
    const int row = blockIdx.x;
    const int t   = threadIdx.x;
    const float4* A4 = (const float4*)(a + (size_t)row * EE);

    float4 x = A4[t];
    uint2 bp = ((const uint2*)(bres16 + (size_t)row * EE))[t];
    __half2 b0 = *reinterpret_cast<__half2*>(&bp.x);
    __half2 b1 = *reinterpret_cast<__half2*>(&bp.y);
    x.x += __half2float(b0.x); x.y += __half2float(b0.y);
    x.z += __half2float(b1.x); x.w += __half2float(b1.y);

    float s  = x.x + x.y + x.z + x.w;
    float ss = x.x * x.x + x.y * x.y + x.z * x.z + x.w * x.w;

#pragma unroll
    for (int off = 16; off > 0; off >>= 1) {
        s  += __shfl_xor_sync(0xffffffffu, s,  off);
        ss += __shfl_xor_sync(0xffffffffu, ss, off);
    }
    __shared__ float sh_s[8], sh_ss[8];
    const int w = t >> 5, l = t & 31;
    if (l == 0) { sh_s[w] = s; sh_ss[w] = ss; }
    __syncthreads();
    s = 0.0f; ss = 0.0f;
#pragma unroll
    for (int i = 0; i < 8; i++) { s += sh_s[i]; ss += sh_ss[i]; }

    const float mean = s * (1.0f / EE);
    const float var  = ss * (1.0f / EE) - mean * mean;
    const float rstd = rsqrtf(var + 1e-5f);

    float4 g4 = ((const float4*)g)[t];
    float4 b4 = ((const float4*)beta)[t];
    float4 o;
    o.x = (x.x - mean) * rstd * g4.x + b4.x;
    o.y = (x.y - mean) * rstd * g4.y + b4.y;
    o.z = (x.z - mean) * rstd * g4.z + b4.z;
    o.w = (x.w - mean) * rstd * g4.w + b4.w;
    ((float4*)(out + (size_t)row * EE))[t] = o;

    if (CVT) {
        uint2 p;
        p.x = packh2(o.x, o.y);
        p.y = packh2(o.z, o.w);
        ((uint2*)(o16 + (size_t)row * EE))[t] = p;
    }
}

// ---------------------------------------------------------------------------
// launch
// ---------------------------------------------------------------------------
extern "C" void kernel_launch(void* const* d_in, const int* in_sizes, int n_in,
                              void* d_out, int out_size)
{
    const float* src    = (const float*)d_in[0];
    const float* in_w   = (const float*)d_in[1];
    const float* in_b   = (const float*)d_in[2];
    const float* out_w  = (const float*)d_in[3];
    const float* out_b  = (const float*)d_in[4];
    const float* ln1g   = (const float*)d_in[5];
    const float* ln1b   = (const float*)d_in[6];
    const float* ln2g   = (const float*)d_in[7];
    const float* ln2b   = (const float*)d_in[8];
    const float* w1     = (const float*)d_in[9];
    const float* b1     = (const float*)d_in[10];
    const float* w2     = (const float*)d_in[11];
    const float* b2     = (const float*)d_in[12];
    float* out = (float*)d_out;

    float* x;
    cudaGetSymbolAddress((void**)&x, g_x);

    __half *qkv16, *src16, *ctx16, *x16, *ff116, *tmp16;
    __half *inw16, *outw16, *w116, *w216;
    cudaGetSymbolAddress((void**)&qkv16, g_qkv16);
    cudaGetSymbolAddress((void**)&src16, g_src16);
    cudaGetSymbolAddress((void**)&ctx16, g_ctx16);
    cudaGetSymbolAddress((void**)&x16,   g_x16);
    cudaGetSymbolAddress((void**)&ff116, g_ff116);
    cudaGetSymbolAddress((void**)&tmp16, g_tmp16);
    cudaGetSymbolAddress((void**)&inw16,  g_inw16);
    cudaGetSymbolAddress((void**)&outw16, g_outw16);
    cudaGetSymbolAddress((void**)&w116,   g_w116);
    cudaGetSymbolAddress((void**)&w216,   g_w216);

    cudaFuncSetAttribute(gemm_mma<1>, cudaFuncAttributeMaxDynamicSharedMemorySize, GSMEM);
    cudaFuncSetAttribute(gemm_mma<2>, cudaFuncAttributeMaxDynamicSharedMemorySize, GSMEM);

    // 0. one-time fp16 converts (weights + src)
    auto cvt = [&](const float* p, __half* o, size_t n) {
        int n4 = (int)(n / 4);
        cvt_kernel<<<(n4 + 255) / 256, 256>>>(p, o, n4);
    };
    cvt(in_w,  inw16,  (size_t)E3 * EE);
    cvt(out_w, outw16, (size_t)EE * EE);
    cvt(w1,    w116,   (size_t)DFF * EE);
    cvt(w2,    w216,   (size_t)EE * DFF);
    cvt(src,   src16,  (size_t)MTOK * EE);

    // 1. qkv = src @ in_proj_w^T + b        (8192 x 3072 x 1024) -> fp16
    gemm_mma<2><<<dim3(E3 / 128, MTOK / 128), 256, GSMEM>>>(
        src16, inw16, in_b, qkv16, E3, EE);
    // 2. flash attention (mma.sync fp16) -> ctx fp16
    attn_mma<<<BB * HH * 16, 128>>>(qkv16, ctx16);
    // 3. attn_out = ctx @ out_w^T + out_b   (8192 x 1024 x 1024) -> fp16 tmp16
    gemm_mma<2><<<dim3(EE / 128, MTOK / 128), 256, GSMEM>>>(
        ctx16, outw16, out_b, tmp16, EE, EE);
    // 4. x = LN1(src + tmp16) -> fp32 x + fp16 x16
    add_ln_kernel<1><<<MTOK, 256>>>(src, tmp16, ln1g, ln1b, x, x16);
    // 5. ff1 = relu(x @ w1^T + b1)          (8192 x 4096 x 1024) -> fp16
    gemm_mma<1><<<dim3(DFF / 128, MTOK / 128), 256, GSMEM>>>(
        x16, w116, b1, ff116, DFF, EE);
    // 6. ff2 = ff1 @ w2^T + b2              (8192 x 1024 x 4096) -> fp16 tmp16
    gemm_mma<2><<<dim3(EE / 128, MTOK / 128), 256, GSMEM>>>(
        ff116, w216, b2, tmp16, EE, DFF);
    // 7. out = LN2(x + tmp16)
    add_ln_kernel<0><<<MTOK, 256>>>(x, tmp16, ln2g, ln2b, out, nullptr);
}

// round 16
// speedup vs baseline: 9.3869x; 1.0109x over previous
#include <cuda_runtime.h>
#include <cuda_fp16.h>
#include <cstdint>
#include <cstddef>

// Problem constants
#define SQ   1024
#define BB   8
#define EE   1024
#define HH   16
#define DD   64
#define DFF  4096
#define MTOK (SQ * BB)     // 8192
#define E3   (3 * EE)      // 3072

// ---------------------------------------------------------------------------
// Scratch (__device__ globals; no allocations allowed)
// ---------------------------------------------------------------------------
__device__ float g_x[(size_t)MTOK * EE];

// fp16 single-plane activations
__device__ __half g_qkv16[(size_t)MTOK * E3];
__device__ __half g_src16[(size_t)MTOK * EE];
__device__ __half g_ctx16[(size_t)MTOK * EE];
__device__ __half g_x16  [(size_t)MTOK * EE];
__device__ __half g_ff116[(size_t)MTOK * DFF];
__device__ __half g_tmp16[(size_t)MTOK * EE];

// fp16 weights (single plane)
__device__ __half g_inw16[(size_t)E3 * EE];
__device__ __half g_outw16[(size_t)EE * EE];
__device__ __half g_w116[(size_t)DFF * EE];
__device__ __half g_w216[(size_t)EE * DFF];

// ---------------------------------------------------------------------------
// helpers
// ---------------------------------------------------------------------------
__device__ __forceinline__ uint32_t smem_u32(const void* p) {
    uint32_t a;
    asm("{ .reg .u64 t; cvta.to.shared.u64 t, %1; cvt.u32.u64 %0, t; }"
        : "=r"(a) : "l"(p));
    return a;
}
__device__ __forceinline__ void cpasync16(uint32_t s, const void* g) {
    asm volatile("cp.async.cg.shared.global [%0], [%1], 16;" :: "r"(s), "l"(g));
}
__device__ __forceinline__ void ldsm4(uint32_t r[4], uint32_t addr) {
    asm volatile("ldmatrix.sync.aligned.m8n8.x4.shared.b16 {%0,%1,%2,%3}, [%4];"
                 : "=r"(r[0]), "=r"(r[1]), "=r"(r[2]), "=r"(r[3]) : "r"(addr));
}
__device__ __forceinline__ void ldsm4t(uint32_t r[4], uint32_t addr) {
    asm volatile("ldmatrix.sync.aligned.m8n8.x4.trans.shared.b16 {%0,%1,%2,%3}, [%4];"
                 : "=r"(r[0]), "=r"(r[1]), "=r"(r[2]), "=r"(r[3]) : "r"(addr));
}
__device__ __forceinline__ void mma16816(float c[4], const uint32_t a[4],
                                         uint32_t b0, uint32_t b1) {
    asm volatile(
        "mma.sync.aligned.m16n8k16.row.col.f32.f16.f16.f32 "
        "{%0,%1,%2,%3}, {%4,%5,%6,%7}, {%8,%9}, {%0,%1,%2,%3};"
        : "+f"(c[0]), "+f"(c[1]), "+f"(c[2]), "+f"(c[3])
        : "r"(a[0]), "r"(a[1]), "r"(a[2]), "r"(a[3]), "r"(b0), "r"(b1));
}
__device__ __forceinline__ uint32_t packh2(float x, float y) {
    __half2 h = __floats2half2_rn(x, y);
    return *reinterpret_cast<uint32_t*>(&h);
}
// 2^x via MUFU (operand already in log2 domain)
__device__ __forceinline__ float ex2(float x) {
    float r;
    asm("ex2.approx.f32 %0, %1;" : "=f"(r) : "f"(x));
    return r;
}

// ---------------------------------------------------------------------------
// fp32 -> fp16 convert (weights + src, one-time per launch)
// ---------------------------------------------------------------------------
__global__ __launch_bounds__(256)
void cvt_kernel(const float* __restrict__ in, __half* __restrict__ o, int n4)
{
    int i = blockIdx.x * blockDim.x + threadIdx.x;
    if (i >= n4) return;
    float4 v = ((const float4*)in)[i];
    uint2 p;
    p.x = packh2(v.x, v.y);
    p.y = packh2(v.z, v.w);
    ((uint2*)o)[i] = p;
}

// ---------------------------------------------------------------------------
// Tensor-core GEMM, fp16 single-pass: C = A[M,K] @ B[N,K]^T + bias
// CTA 128x128, BK=64, 256 threads (8 warps, warp tile 32x64).
// cp.async 2-stage pipeline, ONE __syncthreads per K-iteration:
//   wait_group 0 -> sync -> issue(next) -> compute.
// EPI: 1 = bias+relu -> fp16 C16;  2 = bias -> fp16 C16
// ---------------------------------------------------------------------------
#define TSTRIDE 144
#define PLANE   (128 * TSTRIDE)          // 18432 B
#define STAGE   (2 * PLANE)              // A, B = 36864 B
#define GSMEM   (2 * STAGE)              // 73728 B

template <int EPI>
__global__ __launch_bounds__(256, 2)
void gemm_mma(const __half* __restrict__ Ag, const __half* __restrict__ Bg,
              const float* __restrict__ bias,
              __half* __restrict__ C16,
              int Ndim, int Kdim)
{
    extern __shared__ char sm[];
    const int t    = threadIdx.x;
    const int lane = t & 31;
    const int wid  = t >> 5;
    const int wm   = (wid & 3) * 32;
    const int wn   = (wid >> 2) * 64;
    const int bm   = blockIdx.y * 128;
    const int bn   = blockIdx.x * 128;

    const uint32_t smb = smem_u32(sm);

    auto issue = [&](int k0, int buf) {
        uint32_t sb = smb + buf * STAGE;
#pragma unroll
        for (int i = 0; i < 4; i++) {
            int e = t + i * 256;                  // 0..1023
            int r = e >> 3, c = e & 7;            // r 0..127, c 0..7 (16B units)
            uint32_t off = (uint32_t)(r * TSTRIDE + c * 16);
            size_t ga = (size_t)(bm + r) * Kdim + k0 + c * 8;
            size_t gb = (size_t)(bn + r) * Kdim + k0 + c * 8;
            cpasync16(sb + off,         Ag + ga);
            cpasync16(sb + PLANE + off, Bg + gb);
        }
        asm volatile("cp.async.commit_group;");
    };

    float acc[2][8][4];
#pragma unroll
    for (int i = 0; i < 2; i++)
#pragma unroll
        for (int j = 0; j < 8; j++)
#pragma unroll
            for (int k = 0; k < 4; k++) acc[i][j][k] = 0.0f;

    const int kc = Kdim / 64;
    issue(0, 0);

    for (int ic = 0; ic < kc; ic++) {
        const int buf = ic & 1;
        // data for chunk ic is the only outstanding group
        asm volatile("cp.async.wait_group 0;");
        __syncthreads();          // all warps done with buf^1 AND chunk ic visible
        if (ic + 1 < kc) issue((ic + 1) * 64, buf ^ 1);

        const uint32_t pA = smb + buf * STAGE;
        const uint32_t pB = pA + PLANE;

#pragma unroll
        for (int ks = 0; ks < 4; ks++) {
            uint32_t Af[2][4];
#pragma unroll
            for (int i = 0; i < 2; i++) {
                uint32_t off = (uint32_t)((wm + i * 16 + (lane & 15)) * TSTRIDE
                               + ks * 32 + ((lane >> 4) << 4));
                ldsm4(Af[i], pA + off);
            }
#pragma unroll
            for (int bh2 = 0; bh2 < 2; bh2++) {
                uint32_t Bf[2][4];
#pragma unroll
                for (int g = 0; g < 2; g++) {
                    int nb = wn + bh2 * 32 + g * 16;
                    uint32_t off = (uint32_t)((nb + (lane & 7) + ((lane >> 4) << 3)) * TSTRIDE
                                   + ks * 32 + (((lane >> 3) & 1) << 4));
                    ldsm4(Bf[g], pB + off);
                }
#pragma unroll
                for (int g = 0; g < 2; g++)
#pragma unroll
                    for (int jj = 0; jj < 2; jj++) {
                        int j = bh2 * 4 + g * 2 + jj;
#pragma unroll
                        for (int i = 0; i < 2; i++)
                            mma16816(acc[i][j], Af[i], Bf[g][jj * 2], Bf[g][jj * 2 + 1]);
                    }
            }
        }
    }

#pragma unroll
    for (int i = 0; i < 2; i++) {
        const int r0 = bm + wm + i * 16 + (lane >> 2);
#pragma unroll
        for (int j = 0; j < 8; j++) {
            const int c = bn + wn + j * 8 + 2 * (lane & 3);
            const float bx = bias[c], by = bias[c + 1];
            float v0x = acc[i][j][0] + bx, v0y = acc[i][j][1] + by;
            float v1x = acc[i][j][2] + bx, v1y = acc[i][j][3] + by;
            if (EPI == 1) {
                v0x = fmaxf(v0x, 0.f); v0y = fmaxf(v0y, 0.f);
                v1x = fmaxf(v1x, 0.f); v1y = fmaxf(v1y, 0.f);
            }
            *(uint32_t*)(C16 + (size_t)r0 * Ndim + c)       = packh2(v0x, v0y);
            *(uint32_t*)(C16 + (size_t)(r0 + 8) * Ndim + c) = packh2(v1x, v1y);
        }
    }
}

// ---------------------------------------------------------------------------
// Flash attention via mma.sync fp16.
// Softmax in log2 domain: scores scaled by 0.125*log2(e), ex2.approx for exp.
// One __syncthreads per key tile (wait -> sync -> issue next -> compute).
// ---------------------------------------------------------------------------
#define ATS 144
#define ATILE (64 * ATS)
#define SCALE_LOG2E 0.18033688011112042f   // 0.125 * log2(e)

__global__ __launch_bounds__(128)
void attn_mma(const __half* __restrict__ qkv, __half* __restrict__ ctx)
{
    __shared__ __align__(16) char smQ[ATILE];
    __shared__ __align__(16) char smK[2][ATILE];
    __shared__ __align__(16) char smV[2][ATILE];

    const int qt = blockIdx.x & 15;
    const int bh = blockIdx.x >> 4;
    const int b  = bh / HH;
    const int h  = bh % HH;
    const int t  = threadIdx.x;
    const int lane = t & 31;
    const int w  = t >> 5;
    const int q0 = w * 16;

    const size_t rowstride = (size_t)BB * E3;
    const __half* Qg = qkv + ((size_t)(qt * 64) * BB + b) * E3 + h * DD;
    const __half* Kg = qkv + (size_t)b * E3 + EE + h * DD;
    const __half* Vg = Kg + EE;

    const uint32_t uQ = smem_u32(smQ);
    const uint32_t uK = smem_u32(smK[0]);
    const uint32_t uV = smem_u32(smV[0]);

    auto issue_kv = [&](int kt, int buf) {
#pragma unroll
        for (int i = 0; i < 4; i++) {
            int e = t + i * 128;
            int r = e >> 3, c = e & 7;
            uint32_t off = (uint32_t)(r * ATS + c * 16) + (uint32_t)(buf * ATILE);
            size_t g = (size_t)(kt * 64 + r) * rowstride + c * 8;
            cpasync16(uK + off, Kg + g);
            cpasync16(uV + off, Vg + g);
        }
        asm volatile("cp.async.commit_group;");
    };

    // group 0: Q + KV tile 0
#pragma unroll
    for (int i = 0; i < 4; i++) {
        int e = t + i * 128;
        int r = e >> 3, c = e & 7;
        uint32_t off = (uint32_t)(r * ATS + c * 16);
        size_t g = (size_t)r * rowstride + c * 8;
        cpasync16(uQ + off, Qg + g);
        cpasync16(uK + off, Kg + g);
        cpasync16(uV + off, Vg + g);
    }
    asm volatile("cp.async.commit_group;");

    uint32_t Aq[4][4];
    float oacc[8][4];
#pragma unroll
    for (int j = 0; j < 8; j++)
#pragma unroll
        for (int e = 0; e < 4; e++) oacc[j][e] = 0.0f;
    float m0 = -1e30f, m1 = -1e30f, l0 = 0.0f, l1 = 0.0f;

    for (int kt = 0; kt < 16; kt++) {
        const int buf = kt & 1;
        asm volatile("cp.async.wait_group 0;");
        __syncthreads();
        if (kt + 1 < 16) issue_kv(kt + 1, buf ^ 1);

        if (kt == 0) {
#pragma unroll
            for (int ks = 0; ks < 4; ks++) {
                uint32_t off = (uint32_t)((q0 + (lane & 15)) * ATS + ks * 32 + ((lane >> 4) << 4));
                ldsm4(Aq[ks], uQ + off);
            }
        }
        const uint32_t pK = uK + buf * ATILE;
        const uint32_t pV = uV + buf * ATILE;

        // S = Q @ K^T
        float sacc[8][4];
#pragma unroll
        for (int j = 0; j < 8; j++)
#pragma unroll
            for (int e = 0; e < 4; e++) sacc[j][e] = 0.0f;
#pragma unroll
        for (int ks = 0; ks < 4; ks++) {
#pragma unroll
            for (int g = 0; g < 4; g++) {
                uint32_t Kf[4];
                uint32_t off = (uint32_t)((g * 16 + (lane & 7) + ((lane >> 4) << 3)) * ATS
                               + ks * 32 + (((lane >> 3) & 1) << 4));
                ldsm4(Kf, pK + off);
                mma16816(sacc[g * 2],     Aq[ks], Kf[0], Kf[1]);
                mma16816(sacc[g * 2 + 1], Aq[ks], Kf[2], Kf[3]);
            }
        }

        // online softmax in log2 domain
        float mx0 = -1e30f, mx1 = -1e30f;
#pragma unroll
        for (int j = 0; j < 8; j++) {
            sacc[j][0] *= SCALE_LOG2E; sacc[j][1] *= SCALE_LOG2E;
            sacc[j][2] *= SCALE_LOG2E; sacc[j][3] *= SCALE_LOG2E;
            mx0 = fmaxf(mx0, fmaxf(sacc[j][0], sacc[j][1]));
            mx1 = fmaxf(mx1, fmaxf(sacc[j][2], sacc[j][3]));
        }
        mx0 = fmaxf(mx0, __shfl_xor_sync(0xffffffffu, mx0, 1));
        mx0 = fmaxf(mx0, __shfl_xor_sync(0xffffffffu, mx0, 2));
        mx1 = fmaxf(mx1, __shfl_xor_sync(0xffffffffu, mx1, 1));
        mx1 = fmaxf(mx1, __shfl_xor_sync(0xffffffffu, mx1, 2));

        float nm0 = fmaxf(m0, mx0), nm1 = fmaxf(m1, mx1);
        float c0 = ex2(m0 - nm0), c1 = ex2(m1 - nm1);

        float s0 = 0.0f, s1 = 0.0f;
        uint32_t Pa[4][4];
#pragma unroll
        for (int j = 0; j < 8; j++) {
            float p0 = ex2(sacc[j][0] - nm0);
            float p1 = ex2(sacc[j][1] - nm0);
            float p2 = ex2(sacc[j][2] - nm1);
            float p3 = ex2(sacc[j][3] - nm1);
            s0 += p0 + p1; s1 += p2 + p3;
            const int ks = j >> 1, hi = j & 1;
            Pa[ks][hi * 2]     = packh2(p0, p1);
            Pa[ks][hi * 2 + 1] = packh2(p2, p3);
        }
        s0 += __shfl_xor_sync(0xffffffffu, s0, 1);
        s0 += __shfl_xor_sync(0xffffffffu, s0, 2);
        s1 += __shfl_xor_sync(0xffffffffu, s1, 1);
        s1 += __shfl_xor_sync(0xffffffffu, s1, 2);

        l0 = l0 * c0 + s0;  l1 = l1 * c1 + s1;
        m0 = nm0;           m1 = nm1;
#pragma unroll
        for (int j = 0; j < 8; j++) {
            oacc[j][0] *= c0; oacc[j][1] *= c0;
            oacc[j][2] *= c1; oacc[j][3] *= c1;
        }

        // O += P @ V
#pragma unroll
        for (int ks = 0; ks < 4; ks++) {
#pragma unroll
            for (int dg = 0; dg < 4; dg++) {
                uint32_t Vf[4];
                uint32_t off = (uint32_t)((ks * 16 + (lane & 7) + (((lane >> 3) & 1) << 3)) * ATS
                               + dg * 32 + ((lane >> 4) << 4));
                ldsm4t(Vf, pV + off);
                mma16816(oacc[dg * 2],     Pa[ks], Vf[0], Vf[1]);
                mma16816(oacc[dg * 2 + 1], Pa[ks], Vf[2], Vf[3]);
            }
        }
    }

    const float i0 = 1.0f / l0, i1 = 1.0f / l1;
    const int r0 = qt * 64 + q0 + (lane >> 2);
#pragma unroll
    for (int j = 0; j < 8; j++) {
        const int col = h * DD + j * 8 + 2 * (lane & 3);
        *(uint32_t*)(ctx + ((size_t)r0 * BB + b) * EE + col) =
            packh2(oacc[j][0] * i0, oacc[j][1] * i0);
        *(uint32_t*)(ctx + ((size_t)(r0 + 8) * BB + b) * EE + col) =
            packh2(oacc[j][2] * i1, oacc[j][3] * i1);
    }
}

// ---------------------------------------------------------------------------
// out = layernorm(a + bres16) * g + beta; residual read as fp16.
// CVT=1 also writes fp16 plane.
// ---------------------------------------------------------------------------
template <int CVT>
__global__ __launch_bounds__(256)
void add_ln_kernel(const float* __restrict__ a, const __half* __restrict__ bres16,
                   const float* __restrict__ g, const float* __restrict__ beta,
                   float* __restrict__ out, __half* __restrict__ o16)
{
    const int row = blockIdx.x;
    const int t   = threadIdx.x;
    const float4* A4 = (const float4*)(a + (size_t)row * EE);

    float4 x = A4[t];
    uint2 bp = ((const uint2*)(bres16 + (size_t)row * EE))[t];
    __half2 b0 = *reinterpret_cast<__half2*>(&bp.x);
    __half2 b1 = *reinterpret_cast<__half2*>(&bp.y);
    x.x += __half2float(b0.x); x.y += __half2float(b0.y);
    x.z += __half2float(b1.x); x.w += __half2float(b1.y);

    float s  = x.x + x.y + x.z + x.w;
    float ss = x.x * x.x + x.y * x.y + x.z * x.z + x.w * x.w;

#pragma unroll
    for (int off = 16; off > 0; off >>= 1) {
        s  += __shfl_xor_sync(0xffffffffu, s,  off);
        ss += __shfl_xor_sync(0xffffffffu, ss, off);
    }
    __shared__ float sh_s[8], sh_ss[8];
    const int w = t >> 5, l = t & 31;
    if (l == 0) { sh_s[w] = s; sh_ss[w] = ss; }
    __syncthreads();
    s = 0.0f; ss = 0.0f;
#pragma unroll
    for (int i = 0; i < 8; i++) { s += sh_s[i]; ss += sh_ss[i]; }

    const float mean = s * (1.0f / EE);
    const float var  = ss * (1.0f / EE) - mean * mean;
    const float rstd = rsqrtf(var + 1e-5f);

    float4 g4 = ((const float4*)g)[t];
    float4 b4 = ((const float4*)beta)[t];
    float4 o;
    o.x = (x.x - mean) * rstd * g4.x + b4.x;
    o.y = (x.y - mean) * rstd * g4.y + b4.y;
    o.z = (x.z - mean) * rstd * g4.z + b4.z;
    o.w = (x.w - mean) * rstd * g4.w + b4.w;
    ((float4*)(out + (size_t)row * EE))[t] = o;

    if (CVT) {
        uint2 p;
        p.x = packh2(o.x, o.y);
        p.y = packh2(o.z, o.w);
        ((uint2*)(o16 + (size_t)row * EE))[t] = p;
    }
}

// ---------------------------------------------------------------------------
// launch
// ---------------------------------------------------------------------------
extern "C" void kernel_launch(void* const* d_in, const int* in_sizes, int n_in,
                              void* d_out, int out_size)
{
    const float* src    = (const float*)d_in[0];
    const float* in_w   = (const float*)d_in[1];
    const float* in_b   = (const float*)d_in[2];
    const float* out_w  = (const float*)d_in[3];
    const float* out_b  = (const float*)d_in[4];
    const float* ln1g   = (const float*)d_in[5];
    const float* ln1b   = (const float*)d_in[6];
    const float* ln2g   = (const float*)d_in[7];
    const float* ln2b   = (const float*)d_in[8];
    const float* w1     = (const float*)d_in[9];
    const float* b1     = (const float*)d_in[10];
    const float* w2     = (const float*)d_in[11];
    const float* b2     = (const float*)d_in[12];
    float* out = (float*)d_out;

    float* x;
    cudaGetSymbolAddress((void**)&x, g_x);

    __half *qkv16, *src16, *ctx16, *x16, *ff116, *tmp16;
    __half *inw16, *outw16, *w116, *w216;
    cudaGetSymbolAddress((void**)&qkv16, g_qkv16);
    cudaGetSymbolAddress((void**)&src16, g_src16);
    cudaGetSymbolAddress((void**)&ctx16, g_ctx16);
    cudaGetSymbolAddress((void**)&x16,   g_x16);
    cudaGetSymbolAddress((void**)&ff116, g_ff116);
    cudaGetSymbolAddress((void**)&tmp16, g_tmp16);
    cudaGetSymbolAddress((void**)&inw16,  g_inw16);
    cudaGetSymbolAddress((void**)&outw16, g_outw16);
    cudaGetSymbolAddress((void**)&w116,   g_w116);
    cudaGetSymbolAddress((void**)&w216,   g_w216);

    cudaFuncSetAttribute(gemm_mma<1>, cudaFuncAttributeMaxDynamicSharedMemorySize, GSMEM);
    cudaFuncSetAttribute(gemm_mma<2>, cudaFuncAttributeMaxDynamicSharedMemorySize, GSMEM);

    // 0. one-time fp16 converts (weights + src)
    auto cvt = [&](const float* p, __half* o, size_t n) {
        int n4 = (int)(n / 4);
        cvt_kernel<<<(n4 + 255) / 256, 256>>>(p, o, n4);
    };
    cvt(in_w,  inw16,  (size_t)E3 * EE);
    cvt(out_w, outw16, (size_t)EE * EE);
    cvt(w1,    w116,   (size_t)DFF * EE);
    cvt(w2,    w216,   (size_t)EE * DFF);
    cvt(src,   src16,  (size_t)MTOK * EE);

    // 1. qkv = src @ in_proj_w^T + b        (8192 x 3072 x 1024) -> fp16
    gemm_mma<2><<<dim3(E3 / 128, MTOK / 128), 256, GSMEM>>>(
        src16, inw16, in_b, qkv16, E3, EE);
    // 2. flash attention (mma.sync fp16) -> ctx fp16
    attn_mma<<<BB * HH * 16, 128>>>(qkv16, ctx16);
    // 3. attn_out = ctx @ out_w^T + out_b   (8192 x 1024 x 1024) -> fp16 tmp16
    gemm_mma<2><<<dim3(EE / 128, MTOK / 128), 256, GSMEM>>>(
        ctx16, outw16, out_b, tmp16, EE, EE);
    // 4. x = LN1(src + tmp16) -> fp32 x + fp16 x16
    add_ln_kernel<1><<<MTOK, 256>>>(src, tmp16, ln1g, ln1b, x, x16);
    // 5. ff1 = relu(x @ w1^T + b1)          (8192 x 4096 x 1024) -> fp16
    gemm_mma<1><<<dim3(DFF / 128, MTOK / 128), 256, GSMEM>>>(
        x16, w116, b1, ff116, DFF, EE);
    // 6. ff2 = ff1 @ w2^T + b2              (8192 x 1024 x 4096) -> fp16 tmp16
    gemm_mma<2><<<dim3(EE / 128, MTOK / 128), 256, GSMEM>>>(
        ff116, w216, b2, tmp16, EE, DFF);
    // 7. out = LN2(x + tmp16)
    add_ln_kernel<0><<<MTOK, 256>>>(x, tmp16, ln2g, ln2b, out, nullptr);
}